// round 11
// baseline (speedup 1.0000x reference)
#include <cuda_runtime.h>
#include <cuda_bf16.h>
#include <cstdint>
#include <math.h>

#define BB   16
#define NPTS 4096
#define MPTS 1024
#define CH   256     // C1 = C2 = H1 = H2
#define LDW1 512     // w1 row stride (Cin)

// ---------------------------------------------------------------------------
// Scratch (static device globals)
// ---------------------------------------------------------------------------
__device__ int            g_idx[BB * NPTS * 3];
__device__ float          g_wts[BB * NPTS * 3];
__device__ float          g_G[BB * MPTS * CH];         // [b][m][o] fp32
__device__ __nv_bfloat16  g_Hhi[BB * NPTS * CH];       // [b][n][k]
__device__ __nv_bfloat16  g_Hlo[BB * NPTS * CH];
__device__ __nv_bfloat16  g_X1hi[BB * NPTS * CH];      // feat1^T  [b][n][k]
__device__ __nv_bfloat16  g_X1lo[BB * NPTS * CH];
__device__ __nv_bfloat16  g_X2hi[BB * MPTS * CH];      // feat2^T  [b][m][k]
__device__ __nv_bfloat16  g_X2lo[BB * MPTS * CH];
__device__ __nv_bfloat16  g_W1ahi[CH * CH], g_W1alo[CH * CH];
__device__ __nv_bfloat16  g_W1bhi[CH * CH], g_W1blo[CH * CH];
__device__ __nv_bfloat16  g_W2hi[CH * CH],  g_W2lo[CH * CH];

// ---------------------------------------------------------------------------
// PTX helpers (sm_80-baseline features only — valid on plain sm_100)
// ---------------------------------------------------------------------------
__device__ __forceinline__ uint32_t smem_u32(const void* p) {
    uint32_t a;
    asm("{ .reg .u64 t; cvta.to.shared.u64 t, %1; cvt.u32.u64 %0, t; }"
        : "=r"(a) : "l"(p));
    return a;
}
__device__ __forceinline__ void cp_async16(uint32_t saddr, const void* g) {
    asm volatile("cp.async.cg.shared.global [%0], [%1], 16;"
                 :: "r"(saddr), "l"(g) : "memory");
}
__device__ __forceinline__ void cp_commit() {
    asm volatile("cp.async.commit_group;" ::: "memory");
}
__device__ __forceinline__ void cp_wait1() {
    asm volatile("cp.async.wait_group 1;" ::: "memory");
}
__device__ __forceinline__ void ldm_x4(uint32_t* r, uint32_t addr) {
    asm volatile("ldmatrix.sync.aligned.m8n8.x4.shared.b16 {%0,%1,%2,%3}, [%4];"
                 : "=r"(r[0]), "=r"(r[1]), "=r"(r[2]), "=r"(r[3]) : "r"(addr));
}
__device__ __forceinline__ void mma_bf16(float* d, const uint32_t* a, const uint32_t* b) {
    asm volatile(
        "mma.sync.aligned.m16n8k16.row.col.f32.bf16.bf16.f32 "
        "{%0,%1,%2,%3}, {%4,%5,%6,%7}, {%8,%9}, {%0,%1,%2,%3};"
        : "+f"(d[0]), "+f"(d[1]), "+f"(d[2]), "+f"(d[3])
        : "r"(a[0]), "r"(a[1]), "r"(a[2]), "r"(a[3]), "r"(b[0]), "r"(b[1]));
}

// ---------------------------------------------------------------------------
// Kernel A: merged prep — kNN + 3 weight splits + 2 feature transpose/splits.
// ---------------------------------------------------------------------------
#define PREP_KNN_BLKS    256
#define PREP_SPLIT_BLKS  768
#define PREP_T2_BLKS     4096
#define PREP_TOTAL       (PREP_KNN_BLKS + PREP_SPLIT_BLKS + PREP_T2_BLKS + 16384)

__device__ __forceinline__ void do_transpose_split(
    const float* __restrict__ Xb, int nn, int n0, int k0,
    __nv_bfloat16* __restrict__ Th, __nv_bfloat16* __restrict__ Tl,
    float (*s)[33], int tx, int ty)
{
    #pragma unroll
    for (int j = 0; j < 4; ++j) {
        const int kl = ty + j * 8;
        s[kl][tx] = Xb[(size_t)(k0 + kl) * nn + n0 + tx];
    }
    __syncthreads();
    #pragma unroll
    for (int j = 0; j < 4; ++j) {
        const int nl = ty + j * 8;
        const float v = s[tx][nl];
        const __nv_bfloat16 hi = __float2bfloat16(v);
        const __nv_bfloat16 lo = __float2bfloat16(v - __bfloat162float(hi));
        const size_t a = (size_t)(n0 + nl) * CH + k0 + tx;
        Th[a] = hi; Tl[a] = lo;
    }
}

__global__ __launch_bounds__(256)
void prep_kernel(const float* __restrict__ xyz1,  const float* __restrict__ xyz2,
                 const float* __restrict__ feat1, const float* __restrict__ feat2,
                 const float* __restrict__ w1,    const float* __restrict__ w2)
{
    __shared__ char smbuf[MPTS * 16];      // 16 KB: float4[MPTS] / float[32][33]
    const int bid = blockIdx.x;
    const int t   = threadIdx.x;

    if (bid < PREP_KNN_BLKS) {
        // ---------------- kNN ----------------
        float4* s4 = (float4*)smbuf;
        const int b = bid >> 4;            // 16 batches
        const int g = bid & 15;            // 16 n-blocks of 256

        for (int m = t; m < MPTS; m += 256) {
            const float* q = xyz2 + ((size_t)b * MPTS + m) * 3;
            const float x = q[0], y = q[1], z = q[2];
            s4[m] = make_float4(x, y, z, x * x + y * y + z * z);
        }
        __syncthreads();

        const int n = g * 256 + t;
        const float* p = xyz1 + ((size_t)b * NPTS + n) * 3;
        const float px = p[0], py = p[1], pz = p[2];
        const float qx2 = -2.0f * px, qy2 = -2.0f * py, qz2 = -2.0f * pz;
        const float qsq = px * px + py * py + pz * pz;

        float d0 = 3.4e38f, d1 = 3.4e38f, d2 = 3.4e38f;
        int   i0 = 0, i1 = 0, i2 = 0;

        #pragma unroll 4
        for (int m = 0; m < MPTS; ++m) {
            const float4 v = s4[m];
            float d = v.w;
            d = fmaf(qx2, v.x, d);
            d = fmaf(qy2, v.y, d);
            d = fmaf(qz2, v.z, d);
            if (d < d2) {
                if (d < d0)      { d2 = d1; i2 = i1; d1 = d0; i1 = i0; d0 = d; i0 = m; }
                else if (d < d1) { d2 = d1; i2 = i1; d1 = d;  i1 = m; }
                else             { d2 = d;  i2 = m; }
            }
        }

        d0 += qsq; d1 += qsq; d2 += qsq;
        const float wa = 1.0f / (d0 + 1e-8f);
        const float wb = 1.0f / (d1 + 1e-8f);
        const float wc = 1.0f / (d2 + 1e-8f);
        const float ws = 1.0f / (wa + wb + wc);

        const size_t o = ((size_t)b * NPTS + n) * 3;
        g_idx[o + 0] = i0; g_idx[o + 1] = i1; g_idx[o + 2] = i2;
        g_wts[o + 0] = wa * ws; g_wts[o + 1] = wb * ws; g_wts[o + 2] = wc * ws;
        return;
    }

    float (*s)[33] = (float (*)[33])smbuf;

    if (bid < PREP_KNN_BLKS + PREP_SPLIT_BLKS) {
        const int local = bid - PREP_KNN_BLKS;
        const int which = local >> 8;          // 0,1,2
        const int idx   = (local & 255) * 256 + t;
        const int o = idx >> 8, k = idx & 255;
        float v;
        __nv_bfloat16 *dh, *dl;
        if (which == 0)      { v = w1[(size_t)o * LDW1 + k];       dh = g_W1ahi; dl = g_W1alo; }
        else if (which == 1) { v = w1[(size_t)o * LDW1 + 256 + k]; dh = g_W1bhi; dl = g_W1blo; }
        else                 { v = w2[(size_t)o * CH + k];         dh = g_W2hi;  dl = g_W2lo;  }
        const __nv_bfloat16 hi = __float2bfloat16(v);
        const __nv_bfloat16 lo = __float2bfloat16(v - __bfloat162float(hi));
        dh[idx] = hi; dl[idx] = lo;
    } else if (bid < PREP_KNN_BLKS + PREP_SPLIT_BLKS + PREP_T2_BLKS) {
        const int local = bid - PREP_KNN_BLKS - PREP_SPLIT_BLKS;
        const int n0 = (local & 31) * 32;              // MPTS/32 = 32
        const int k0 = ((local >> 5) & 7) * 32;        // CH/32 = 8
        const int b  = local >> 8;
        do_transpose_split(feat2 + (size_t)b * CH * MPTS, MPTS, n0, k0,
                           g_X2hi + (size_t)b * MPTS * CH,
                           g_X2lo + (size_t)b * MPTS * CH,
                           s, t & 31, t >> 5);
    } else {
        const int local = bid - PREP_KNN_BLKS - PREP_SPLIT_BLKS - PREP_T2_BLKS;
        const int n0 = (local & 127) * 32;             // NPTS/32 = 128
        const int k0 = ((local >> 7) & 7) * 32;
        const int b  = local >> 10;
        do_transpose_split(feat1 + (size_t)b * CH * NPTS, NPTS, n0, k0,
                           g_X1hi + (size_t)b * NPTS * CH,
                           g_X1lo + (size_t)b * NPTS * CH,
                           s, t & 31, t >> 5);
    }
}

// ---------------------------------------------------------------------------
// Tensor-core GEMM via mma.sync bf16 (split hi/lo, 3 terms).
//   XOR-swizzled smem (64B pitch), 3-stage cp.async pipeline (wait_group 1).
//   Unified store-first smem-staged epilogue:
//     acc -> S[Bcol][Arow], then per-warp coalesced row readback.
//   MODE 0: plain fp32 rows -> Out                           (G GEMM)
//   MODE 1: per-row BN+ReLU fp32 rows -> Out                 (GEMM2 -> out)
//   MODE 2: interp-add + BN + ReLU + bf16-split -> g_H*      (F GEMM)
// ---------------------------------------------------------------------------
#define KTOT    256
#define KC      32
#define NCHUNK  (KTOT / KC)
#define ARR_B   (128 * 64)               // 8192  (128 rows x 64B)
#define STAGE_B (4 * ARR_B)              // 32768
#define NSTAGE  3
#define SMEM_GEMM (NSTAGE * STAGE_B)     // 98304  (>= 128*132*4 = 67584 for S)
#define SPITCH  132

__device__ __forceinline__ uint32_t swz(int row, int chunk) {
    return (uint32_t)(row * 64 + ((chunk ^ ((row >> 1) & 3)) << 4));
}

template<int MODE>
__global__ __launch_bounds__(256, 2)
void mma_gemm(const __nv_bfloat16* __restrict__ Ahi, const __nv_bfloat16* __restrict__ Alo,
              size_t aBS,
              const __nv_bfloat16* __restrict__ Bhi, const __nv_bfloat16* __restrict__ Blo,
              size_t bBS,
              float* __restrict__ Out, size_t oBS, int outLd,
              const float* __restrict__ gamma, const float* __restrict__ beta)
{
    extern __shared__ char sm[];
    const uint32_t sb = smem_u32(sm);

    const int tid  = threadIdx.x;
    const int warp = tid >> 5;
    const int lane = tid & 31;
    const int wm   = warp & 3;           // 4 warps over A-rows
    const int wn   = warp >> 2;          // 2 warps over B-cols
    const int bz   = blockIdx.z;

    const __nv_bfloat16* srcs[4] = {
        Ahi + bz * aBS + (size_t)(blockIdx.y * 128) * KTOT,
        Alo + bz * aBS + (size_t)(blockIdx.y * 128) * KTOT,
        Bhi + bz * bBS + (size_t)(blockIdx.x * 128) * KTOT,
        Blo + bz * bBS + (size_t)(blockIdx.x * 128) * KTOT };

    auto load_stage = [&](int c) {
        const int k0 = c * KC;
        const uint32_t stage = sb + (c % NSTAGE) * STAGE_B;
        #pragma unroll
        for (int i = 0; i < 8; ++i) {
            const int id  = tid + i * 256;
            const int arr = id >> 9;
            const int id9 = id & 511;
            const int row = id9 >> 2;
            const int ch  = id9 & 3;
            cp_async16(stage + arr * ARR_B + swz(row, ch),
                       srcs[arr] + (size_t)row * KTOT + k0 + ch * 8);
        }
        cp_commit();
    };

    float acc[2][8][4];
    #pragma unroll
    for (int a = 0; a < 2; ++a)
        #pragma unroll
        for (int b = 0; b < 8; ++b)
            #pragma unroll
            for (int d = 0; d < 4; ++d) acc[a][b][d] = 0.0f;

    load_stage(0);
    load_stage(1);

    for (int c = 0; c < NCHUNK; ++c) {
        cp_wait1();
        __syncthreads();
        if (c + 2 < NCHUNK) load_stage(c + 2);
        else                cp_commit();

        const uint32_t stage = sb + (c % NSTAGE) * STAGE_B;
        const uint32_t aHb = stage;
        const uint32_t aLb = stage + ARR_B;
        const uint32_t bHb = stage + 2 * ARR_B;
        const uint32_t bLb = stage + 3 * ARR_B;

        #pragma unroll
        for (int s = 0; s < 2; ++s) {
            uint32_t ah[2][4], al[2][4];
            {
                const int arow  = wm * 32 + (lane & 15);
                const int achnk = s * 2 + ((lane >> 4) & 1);
                ldm_x4(ah[0], aHb + swz(arow,      achnk));
                ldm_x4(ah[1], aHb + swz(arow + 16, achnk));
                ldm_x4(al[0], aLb + swz(arow,      achnk));
                ldm_x4(al[1], aLb + swz(arow + 16, achnk));
            }
            #pragma unroll
            for (int nt = 0; nt < 4; ++nt) {
                uint32_t bh[4], bl[4];
                const int brow  = wn * 64 + nt * 16 + ((lane >> 4) << 3) + (lane & 7);
                const int bchnk = s * 2 + ((lane >> 3) & 1);
                ldm_x4(bh, bHb + swz(brow, bchnk));
                ldm_x4(bl, bLb + swz(brow, bchnk));
                // mi-innermost: same-accumulator reuse distance = 4
                mma_bf16(acc[0][2*nt],   ah[0], bh);
                mma_bf16(acc[1][2*nt],   ah[1], bh);
                mma_bf16(acc[0][2*nt+1], ah[0], bh + 2);
                mma_bf16(acc[1][2*nt+1], ah[1], bh + 2);
                mma_bf16(acc[0][2*nt],   ah[0], bl);
                mma_bf16(acc[1][2*nt],   ah[1], bl);
                mma_bf16(acc[0][2*nt+1], ah[0], bl + 2);
                mma_bf16(acc[1][2*nt+1], ah[1], bl + 2);
                mma_bf16(acc[0][2*nt],   al[0], bh);
                mma_bf16(acc[1][2*nt],   al[1], bh);
                mma_bf16(acc[0][2*nt+1], al[0], bh + 2);
                mma_bf16(acc[1][2*nt+1], al[1], bh + 2);
            }
        }
    }

    // --------------- unified store-first staged epilogue -------------------
    __syncthreads();                      // all warps done with stage smem
    float* S = (float*)sm;                // [128 Bcol][SPITCH] fp32

    #pragma unroll
    for (int mi = 0; mi < 2; ++mi) {
        const int ol = wm * 32 + mi * 16 + (lane >> 2);      // A-row local
        #pragma unroll
        for (int nt = 0; nt < 8; ++nt) {
            const int cl = wn * 64 + nt * 8 + (lane & 3) * 2; // B-col local
            S[cl * SPITCH + ol]           = acc[mi][nt][0];
            S[(cl + 1) * SPITCH + ol]     = acc[mi][nt][1];
            S[cl * SPITCH + ol + 8]       = acc[mi][nt][2];
            S[(cl + 1) * SPITCH + ol + 8] = acc[mi][nt][3];
        }
    }
    __syncthreads();

    const float inv = 1.0f / sqrtf(1.0f + 1e-5f);

    if (MODE == 2) {
        // interp-add + BN + ReLU + bf16-split  (A-rows = o, B-cols = n)
        const int n0 = blockIdx.x * 128;
        const int o0 = blockIdx.y * 128;
        const float* Gb = g_G + (size_t)bz * MPTS * CH;
        const float4 gm = *(const float4*)&gamma[o0 + 4 * lane];
        const float4 bt = *(const float4*)&beta[o0 + 4 * lane];

        for (int j = 0; j < 16; ++j) {
            const int nl = warp * 16 + j;
            const size_t pb = (size_t)bz * NPTS + n0 + nl;
            const int   i0 = g_idx[pb * 3 + 0];
            const int   i1 = g_idx[pb * 3 + 1];
            const int   i2 = g_idx[pb * 3 + 2];
            const float w0 = g_wts[pb * 3 + 0];
            const float w1 = g_wts[pb * 3 + 1];
            const float w2 = g_wts[pb * 3 + 2];
            const float4 a4 = *(const float4*)(Gb + (size_t)i0 * CH + o0 + 4 * lane);
            const float4 b4 = *(const float4*)(Gb + (size_t)i1 * CH + o0 + 4 * lane);
            const float4 c4 = *(const float4*)(Gb + (size_t)i2 * CH + o0 + 4 * lane);
            float4 v = *(float4*)&S[nl * SPITCH + 4 * lane];
            v.x += w0 * a4.x + w1 * b4.x + w2 * c4.x;
            v.y += w0 * a4.y + w1 * b4.y + w2 * c4.y;
            v.z += w0 * a4.z + w1 * b4.z + w2 * c4.z;
            v.w += w0 * a4.w + w1 * b4.w + w2 * c4.w;
            v.x = fmaxf(fmaf(v.x, gm.x * inv, bt.x), 0.0f);
            v.y = fmaxf(fmaf(v.y, gm.y * inv, bt.y), 0.0f);
            v.z = fmaxf(fmaf(v.z, gm.z * inv, bt.z), 0.0f);
            v.w = fmaxf(fmaf(v.w, gm.w * inv, bt.w), 0.0f);
            __nv_bfloat16 h[4], l[4];
            h[0] = __float2bfloat16(v.x); l[0] = __float2bfloat16(v.x - __bfloat162float(h[0]));
            h[1] = __float2bfloat16(v.y); l[1] = __float2bfloat16(v.y - __bfloat162float(h[1]));
            h[2] = __float2bfloat16(v.z); l[2] = __float2bfloat16(v.z - __bfloat162float(h[2]));
            h[3] = __float2bfloat16(v.w); l[3] = __float2bfloat16(v.w - __bfloat162float(h[3]));
            const size_t hb = ((size_t)bz * NPTS + n0 + nl) * CH + o0 + 4 * lane;
            *(__nv_bfloat162*)&g_Hhi[hb]     = __nv_bfloat162(h[0], h[1]);
            *(__nv_bfloat162*)&g_Hhi[hb + 2] = __nv_bfloat162(h[2], h[3]);
            *(__nv_bfloat162*)&g_Hlo[hb]     = __nv_bfloat162(l[0], l[1]);
            *(__nv_bfloat162*)&g_Hlo[hb + 2] = __nv_bfloat162(l[2], l[3]);
        }
        return;
    }

    // MODE 0 / 1: coalesced fp32 row stores; MODE 1 adds per-row BN+ReLU
    const int rA0 = blockIdx.y * 128;     // A-row base (o for G, n for out)
    const int cB0 = blockIdx.x * 128;     // B-col base (m for G, o for out)
    float* outB = Out + bz * oBS;

    for (int j = 0; j < 16; ++j) {
        const int r = warp * 16 + j;      // B-col local index
        float4 v = *(float4*)&S[r * SPITCH + 4 * lane];
        if (MODE == 1) {
            const float sc = __ldg(&gamma[cB0 + r]) * inv;
            const float bb = __ldg(&beta[cB0 + r]);
            v.x = fmaxf(fmaf(v.x, sc, bb), 0.0f);
            v.y = fmaxf(fmaf(v.y, sc, bb), 0.0f);
            v.z = fmaxf(fmaf(v.z, sc, bb), 0.0f);
            v.w = fmaxf(fmaf(v.w, sc, bb), 0.0f);
        }
        *(float4*)&outB[(size_t)(cB0 + r) * outLd + rA0 + 4 * lane] = v;
    }
}

// ---------------------------------------------------------------------------
extern "C" void kernel_launch(void* const* d_in, const int* in_sizes, int n_in,
                              void* d_out, int out_size)
{
    const float* xyz1   = (const float*)d_in[0];
    const float* xyz2   = (const float*)d_in[1];
    const float* feat1  = (const float*)d_in[2];
    const float* feat2  = (const float*)d_in[3];
    const float* w1     = (const float*)d_in[4];
    const float* gamma1 = (const float*)d_in[5];
    const float* beta1  = (const float*)d_in[6];
    const float* w2     = (const float*)d_in[7];
    const float* gamma2 = (const float*)d_in[8];
    const float* beta2  = (const float*)d_in[9];
    float* out = (float*)d_out;

    float *Gp;
    __nv_bfloat16 *X1h, *X1l, *X2h, *X2l, *Hh, *Hl;
    __nv_bfloat16 *W1ah, *W1al, *W1bh, *W1bl, *W2h, *W2l;
    cudaGetSymbolAddress((void**)&Gp,  g_G);
    cudaGetSymbolAddress((void**)&X1h, g_X1hi); cudaGetSymbolAddress((void**)&X1l, g_X1lo);
    cudaGetSymbolAddress((void**)&X2h, g_X2hi); cudaGetSymbolAddress((void**)&X2l, g_X2lo);
    cudaGetSymbolAddress((void**)&Hh,  g_Hhi);  cudaGetSymbolAddress((void**)&Hl,  g_Hlo);
    cudaGetSymbolAddress((void**)&W1ah, g_W1ahi); cudaGetSymbolAddress((void**)&W1al, g_W1alo);
    cudaGetSymbolAddress((void**)&W1bh, g_W1bhi); cudaGetSymbolAddress((void**)&W1bl, g_W1blo);
    cudaGetSymbolAddress((void**)&W2h,  g_W2hi);  cudaGetSymbolAddress((void**)&W2l,  g_W2lo);

    cudaFuncSetAttribute(mma_gemm<0>, cudaFuncAttributeMaxDynamicSharedMemorySize, SMEM_GEMM);
    cudaFuncSetAttribute(mma_gemm<1>, cudaFuncAttributeMaxDynamicSharedMemorySize, SMEM_GEMM);
    cudaFuncSetAttribute(mma_gemm<2>, cudaFuncAttributeMaxDynamicSharedMemorySize, SMEM_GEMM);

    // 1. merged prep: kNN + weight splits + feature transpose/splits
    prep_kernel<<<PREP_TOTAL, 256>>>(xyz1, xyz2, feat1, feat2, w1, w2);

    // 2. G[b][m][o] = W1a @ feat2
    mma_gemm<0><<<dim3(MPTS / 128, CH / 128, BB), 256, SMEM_GEMM>>>(
        W1ah, W1al, 0, X2h, X2l, (size_t)MPTS * CH,
        Gp, (size_t)MPTS * CH, CH, nullptr, nullptr);

    // 3. F GEMM fused with interpolation/BN/ReLU/split -> g_Hhi/g_Hlo
    mma_gemm<2><<<dim3(NPTS / 128, CH / 128, BB), 256, SMEM_GEMM>>>(
        W1bh, W1bl, 0, X1h, X1l, (size_t)NPTS * CH,
        nullptr, 0, 0, gamma1, beta1);

    // 4. Out[b][o][n] = relu(bn(W2 @ H))
    mma_gemm<1><<<dim3(CH / 128, NPTS / 128, BB), 256, SMEM_GEMM>>>(
        Hh, Hl, (size_t)NPTS * CH, W2h, W2l, 0,
        out, (size_t)CH * NPTS, NPTS, gamma2, beta2);

    (void)in_sizes; (void)n_in; (void)out_size;
}

// round 12
// speedup vs baseline: 1.3474x; 1.3474x over previous
#include <cuda_runtime.h>
#include <cuda_fp16.h>
#include <cstdint>
#include <math.h>

#define BB   16
#define NPTS 4096
#define MPTS 1024
#define CH   256     // C1 = C2 = H1 = H2
#define LDW1 512     // w1 row stride (Cin)

// ---------------------------------------------------------------------------
// Scratch (static device globals)
// ---------------------------------------------------------------------------
__device__ int     g_idx[BB * NPTS * 3];
__device__ float   g_wts[BB * NPTS * 3];
__device__ float   g_G[BB * MPTS * CH];        // [b][m][o] fp32
__device__ __half  g_Hf[BB * NPTS * CH];       // [b][n][k] fp16 single
__device__ __half  g_X1f[BB * NPTS * CH];      // feat1^T  [b][n][k] fp16
__device__ __half  g_X2f[BB * MPTS * CH];      // feat2^T  [b][m][k] fp16
__device__ __half  g_W1ahi[CH * CH], g_W1alo[CH * CH];
__device__ __half  g_W1bhi[CH * CH], g_W1blo[CH * CH];
__device__ __half  g_W2hi[CH * CH],  g_W2lo[CH * CH];

// ---------------------------------------------------------------------------
// PTX helpers (sm_80-baseline features only — valid on plain sm_100)
// ---------------------------------------------------------------------------
__device__ __forceinline__ uint32_t smem_u32(const void* p) {
    uint32_t a;
    asm("{ .reg .u64 t; cvta.to.shared.u64 t, %1; cvt.u32.u64 %0, t; }"
        : "=r"(a) : "l"(p));
    return a;
}
__device__ __forceinline__ void cp_async16(uint32_t saddr, const void* g) {
    asm volatile("cp.async.cg.shared.global [%0], [%1], 16;"
                 :: "r"(saddr), "l"(g) : "memory");
}
__device__ __forceinline__ void cp_commit() {
    asm volatile("cp.async.commit_group;" ::: "memory");
}
__device__ __forceinline__ void cp_wait1() {
    asm volatile("cp.async.wait_group 1;" ::: "memory");
}
__device__ __forceinline__ void ldm_x4(uint32_t* r, uint32_t addr) {
    asm volatile("ldmatrix.sync.aligned.m8n8.x4.shared.b16 {%0,%1,%2,%3}, [%4];"
                 : "=r"(r[0]), "=r"(r[1]), "=r"(r[2]), "=r"(r[3]) : "r"(addr));
}
__device__ __forceinline__ void mma_f16(float* d, const uint32_t* a, const uint32_t* b) {
    asm volatile(
        "mma.sync.aligned.m16n8k16.row.col.f32.f16.f16.f32 "
        "{%0,%1,%2,%3}, {%4,%5,%6,%7}, {%8,%9}, {%0,%1,%2,%3};"
        : "+f"(d[0]), "+f"(d[1]), "+f"(d[2]), "+f"(d[3])
        : "r"(a[0]), "r"(a[1]), "r"(a[2]), "r"(a[3]), "r"(b[0]), "r"(b[1]));
}

// ---------------------------------------------------------------------------
// Kernel A: merged prep — kNN + 3 weight hi/lo splits + 2 feature transposes.
// ---------------------------------------------------------------------------
#define PREP_KNN_BLKS    256
#define PREP_SPLIT_BLKS  768
#define PREP_T2_BLKS     4096
#define PREP_TOTAL       (PREP_KNN_BLKS + PREP_SPLIT_BLKS + PREP_T2_BLKS + 16384)

__device__ __forceinline__ void do_transpose_f16(
    const float* __restrict__ Xb, int nn, int n0, int k0,
    __half* __restrict__ T, float (*s)[33], int tx, int ty)
{
    #pragma unroll
    for (int j = 0; j < 4; ++j) {
        const int kl = ty + j * 8;
        s[kl][tx] = Xb[(size_t)(k0 + kl) * nn + n0 + tx];
    }
    __syncthreads();
    #pragma unroll
    for (int j = 0; j < 4; ++j) {
        const int nl = ty + j * 8;
        T[(size_t)(n0 + nl) * CH + k0 + tx] = __float2half(s[tx][nl]);
    }
}

__global__ __launch_bounds__(256)
void prep_kernel(const float* __restrict__ xyz1,  const float* __restrict__ xyz2,
                 const float* __restrict__ feat1, const float* __restrict__ feat2,
                 const float* __restrict__ w1,    const float* __restrict__ w2)
{
    __shared__ char smbuf[MPTS * 16];
    const int bid = blockIdx.x;
    const int t   = threadIdx.x;

    if (bid < PREP_KNN_BLKS) {
        float4* s4 = (float4*)smbuf;
        const int b = bid >> 4;
        const int g = bid & 15;

        for (int m = t; m < MPTS; m += 256) {
            const float* q = xyz2 + ((size_t)b * MPTS + m) * 3;
            const float x = q[0], y = q[1], z = q[2];
            s4[m] = make_float4(x, y, z, x * x + y * y + z * z);
        }
        __syncthreads();

        const int n = g * 256 + t;
        const float* p = xyz1 + ((size_t)b * NPTS + n) * 3;
        const float px = p[0], py = p[1], pz = p[2];
        const float qx2 = -2.0f * px, qy2 = -2.0f * py, qz2 = -2.0f * pz;
        const float qsq = px * px + py * py + pz * pz;

        float d0 = 3.4e38f, d1 = 3.4e38f, d2 = 3.4e38f;
        int   i0 = 0, i1 = 0, i2 = 0;

        #pragma unroll 4
        for (int m = 0; m < MPTS; ++m) {
            const float4 v = s4[m];
            float d = v.w;
            d = fmaf(qx2, v.x, d);
            d = fmaf(qy2, v.y, d);
            d = fmaf(qz2, v.z, d);
            if (d < d2) {
                if (d < d0)      { d2 = d1; i2 = i1; d1 = d0; i1 = i0; d0 = d; i0 = m; }
                else if (d < d1) { d2 = d1; i2 = i1; d1 = d;  i1 = m; }
                else             { d2 = d;  i2 = m; }
            }
        }

        d0 += qsq; d1 += qsq; d2 += qsq;
        const float wa = 1.0f / (d0 + 1e-8f);
        const float wb = 1.0f / (d1 + 1e-8f);
        const float wc = 1.0f / (d2 + 1e-8f);
        const float ws = 1.0f / (wa + wb + wc);

        const size_t o = ((size_t)b * NPTS + n) * 3;
        g_idx[o + 0] = i0; g_idx[o + 1] = i1; g_idx[o + 2] = i2;
        g_wts[o + 0] = wa * ws; g_wts[o + 1] = wb * ws; g_wts[o + 2] = wc * ws;
        return;
    }

    float (*s)[33] = (float (*)[33])smbuf;

    if (bid < PREP_KNN_BLKS + PREP_SPLIT_BLKS) {
        const int local = bid - PREP_KNN_BLKS;
        const int which = local >> 8;
        const int idx   = (local & 255) * 256 + t;
        const int o = idx >> 8, k = idx & 255;
        float v;
        __half *dh, *dl;
        if (which == 0)      { v = w1[(size_t)o * LDW1 + k];       dh = g_W1ahi; dl = g_W1alo; }
        else if (which == 1) { v = w1[(size_t)o * LDW1 + 256 + k]; dh = g_W1bhi; dl = g_W1blo; }
        else                 { v = w2[(size_t)o * CH + k];         dh = g_W2hi;  dl = g_W2lo;  }
        const __half hi = __float2half(v);
        const __half lo = __float2half(v - __half2float(hi));
        dh[idx] = hi; dl[idx] = lo;
    } else if (bid < PREP_KNN_BLKS + PREP_SPLIT_BLKS + PREP_T2_BLKS) {
        const int local = bid - PREP_KNN_BLKS - PREP_SPLIT_BLKS;
        const int n0 = (local & 31) * 32;
        const int k0 = ((local >> 5) & 7) * 32;
        const int b  = local >> 8;
        do_transpose_f16(feat2 + (size_t)b * CH * MPTS, MPTS, n0, k0,
                         g_X2f + (size_t)b * MPTS * CH, s, t & 31, t >> 5);
    } else {
        const int local = bid - PREP_KNN_BLKS - PREP_SPLIT_BLKS - PREP_T2_BLKS;
        const int n0 = (local & 127) * 32;
        const int k0 = ((local >> 7) & 7) * 32;
        const int b  = local >> 10;
        do_transpose_f16(feat1 + (size_t)b * CH * NPTS, NPTS, n0, k0,
                         g_X1f + (size_t)b * NPTS * CH, s, t & 31, t >> 5);
    }
}

// ---------------------------------------------------------------------------
// Tensor-core GEMM, fp16: split operand (hi/lo) x single operand, 2 mma terms.
//   ASPLIT=1: A = weights hi/lo, B = activations single   (G, F GEMMs)
//   ASPLIT=0: A = activations single, B = weights hi/lo   (GEMM2)
//   3 smem arrays/stage, XOR swizzle, 3-stage cp.async pipeline.
//   MODE 0: plain fp32 store        MODE 1: BN+ReLU fp32 store
//   MODE 2: interp-add + BN + ReLU -> fp16 H (R9-style gather-then-add)
// ---------------------------------------------------------------------------
#define KTOT    256
#define KC      32
#define NCHUNK  (KTOT / KC)
#define ARR_B   (128 * 64)               // 8192 (128 rows x 32 fp16 = 64B)
#define STAGE_B (3 * ARR_B)              // 24576
#define NSTAGE  3
#define SMEM_GEMM (NSTAGE * STAGE_B)     // 73728 (>= 128*132*4 = 67584 for S)
#define SPITCH  132

__device__ __forceinline__ uint32_t swz(int row, int chunk) {
    return (uint32_t)(row * 64 + ((chunk ^ ((row >> 1) & 3)) << 4));
}

template<int MODE, int ASPLIT>
__global__ __launch_bounds__(256, 2)
void mma_gemm(const __half* __restrict__ A0, const __half* __restrict__ A1,
              size_t aBS,
              const __half* __restrict__ B0, const __half* __restrict__ B1,
              size_t bBS,
              float* __restrict__ Out, size_t oBS, int outLd,
              const float* __restrict__ gamma, const float* __restrict__ beta)
{
    extern __shared__ char sm[];
    const uint32_t sb = smem_u32(sm);

    const int tid  = threadIdx.x;
    const int warp = tid >> 5;
    const int lane = tid & 31;
    const int wm   = warp & 3;           // 4 warps over A-rows
    const int wn   = warp >> 2;          // 2 warps over B-cols
    const int bz   = blockIdx.z;

    // 3 operand arrays per stage
    const __half* srcs[3];
    if (ASPLIT) {
        srcs[0] = A0 + (size_t)(blockIdx.y * 128) * KTOT;              // W hi
        srcs[1] = A1 + (size_t)(blockIdx.y * 128) * KTOT;              // W lo
        srcs[2] = B0 + bz * bBS + (size_t)(blockIdx.x * 128) * KTOT;   // act
    } else {
        srcs[0] = A0 + bz * aBS + (size_t)(blockIdx.y * 128) * KTOT;   // act
        srcs[1] = B0 + (size_t)(blockIdx.x * 128) * KTOT;              // W hi
        srcs[2] = B1 + (size_t)(blockIdx.x * 128) * KTOT;              // W lo
    }

    auto load_stage = [&](int c) {
        const int k0 = c * KC;
        const uint32_t stage = sb + (c % NSTAGE) * STAGE_B;
        #pragma unroll
        for (int i = 0; i < 6; ++i) {           // 1536 chunks, 6/thread
            const int id  = tid + i * 256;
            const int arr = id >> 9;
            const int id9 = id & 511;
            const int row = id9 >> 2;
            const int ch  = id9 & 3;
            cp_async16(stage + arr * ARR_B + swz(row, ch),
                       srcs[arr] + (size_t)row * KTOT + k0 + ch * 8);
        }
        cp_commit();
    };

    float acc[2][8][4];
    #pragma unroll
    for (int a = 0; a < 2; ++a)
        #pragma unroll
        for (int b = 0; b < 8; ++b)
            #pragma unroll
            for (int d = 0; d < 4; ++d) acc[a][b][d] = 0.0f;

    load_stage(0);
    load_stage(1);

    for (int c = 0; c < NCHUNK; ++c) {
        cp_wait1();
        __syncthreads();
        if (c + 2 < NCHUNK) load_stage(c + 2);
        else                cp_commit();

        const uint32_t stage = sb + (c % NSTAGE) * STAGE_B;
        const uint32_t a0b = stage;              // ASPLIT: Whi | else act
        const uint32_t a1b = stage + ARR_B;      // ASPLIT: Wlo | else Whi
        const uint32_t a2b = stage + 2 * ARR_B;  // ASPLIT: act | else Wlo

        #pragma unroll
        for (int s = 0; s < 2; ++s) {
            const int arow  = wm * 32 + (lane & 15);
            const int achnk = s * 2 + ((lane >> 4) & 1);
            const int brow  = wn * 64 + ((lane >> 4) << 3) + (lane & 7);
            const int bchnk = s * 2 + ((lane >> 3) & 1);

            if (ASPLIT) {
                uint32_t ah[2][4], al[2][4];
                ldm_x4(ah[0], a0b + swz(arow,      achnk));
                ldm_x4(ah[1], a0b + swz(arow + 16, achnk));
                ldm_x4(al[0], a1b + swz(arow,      achnk));
                ldm_x4(al[1], a1b + swz(arow + 16, achnk));
                #pragma unroll
                for (int nt = 0; nt < 4; ++nt) {
                    uint32_t bv[4];
                    ldm_x4(bv, a2b + swz(brow + nt * 16, bchnk));
                    mma_f16(acc[0][2*nt],   ah[0], bv);
                    mma_f16(acc[1][2*nt],   ah[1], bv);
                    mma_f16(acc[0][2*nt+1], ah[0], bv + 2);
                    mma_f16(acc[1][2*nt+1], ah[1], bv + 2);
                    mma_f16(acc[0][2*nt],   al[0], bv);
                    mma_f16(acc[1][2*nt],   al[1], bv);
                    mma_f16(acc[0][2*nt+1], al[0], bv + 2);
                    mma_f16(acc[1][2*nt+1], al[1], bv + 2);
                }
            } else {
                uint32_t av[2][4];
                ldm_x4(av[0], a0b + swz(arow,      achnk));
                ldm_x4(av[1], a0b + swz(arow + 16, achnk));
                #pragma unroll
                for (int nt = 0; nt < 4; ++nt) {
                    uint32_t bh[4], bl[4];
                    ldm_x4(bh, a1b + swz(brow + nt * 16, bchnk));
                    ldm_x4(bl, a2b + swz(brow + nt * 16, bchnk));
                    mma_f16(acc[0][2*nt],   av[0], bh);
                    mma_f16(acc[1][2*nt],   av[1], bh);
                    mma_f16(acc[0][2*nt+1], av[0], bh + 2);
                    mma_f16(acc[1][2*nt+1], av[1], bh + 2);
                    mma_f16(acc[0][2*nt],   av[0], bl);
                    mma_f16(acc[1][2*nt],   av[1], bl);
                    mma_f16(acc[0][2*nt+1], av[0], bl + 2);
                    mma_f16(acc[1][2*nt+1], av[1], bl + 2);
                }
            }
        }
    }

    const float inv = 1.0f / sqrtf(1.0f + 1e-5f);

    if (MODE == 2) {
        // ---- R9-style epilogue: gather interp -> S (high MLP), add acc,
        //      then BN+ReLU+fp16 store ----
        __syncthreads();                 // pipeline smem dead; reuse as S
        float* S = (float*)sm;           // [128 n][SPITCH]
        const int n0 = blockIdx.x * 128;
        const int o0 = blockIdx.y * 128;
        const float* Gb = g_G + (size_t)bz * MPTS * CH;

        for (int j = 0; j < 16; ++j) {
            const int nl = warp * 16 + j;
            const size_t pb = (size_t)bz * NPTS + n0 + nl;
            const int   i0 = g_idx[pb * 3 + 0];
            const int   i1 = g_idx[pb * 3 + 1];
            const int   i2 = g_idx[pb * 3 + 2];
            const float w0 = g_wts[pb * 3 + 0];
            const float w1 = g_wts[pb * 3 + 1];
            const float w2 = g_wts[pb * 3 + 2];
            const float4 a4 = *(const float4*)(Gb + (size_t)i0 * CH + o0 + 4 * lane);
            const float4 b4 = *(const float4*)(Gb + (size_t)i1 * CH + o0 + 4 * lane);
            const float4 c4 = *(const float4*)(Gb + (size_t)i2 * CH + o0 + 4 * lane);
            float4 v;
            v.x = w0 * a4.x + w1 * b4.x + w2 * c4.x;
            v.y = w0 * a4.y + w1 * b4.y + w2 * c4.y;
            v.z = w0 * a4.z + w1 * b4.z + w2 * c4.z;
            v.w = w0 * a4.w + w1 * b4.w + w2 * c4.w;
            *(float4*)&S[nl * SPITCH + 4 * lane] = v;
        }
        __syncthreads();

        #pragma unroll
        for (int mi = 0; mi < 2; ++mi) {
            const int ol = wm * 32 + mi * 16 + (lane >> 2);
            #pragma unroll
            for (int nt = 0; nt < 8; ++nt) {
                const int cl = wn * 64 + nt * 8 + (lane & 3) * 2;
                S[cl * SPITCH + ol]           += acc[mi][nt][0];
                S[(cl + 1) * SPITCH + ol]     += acc[mi][nt][1];
                S[cl * SPITCH + ol + 8]       += acc[mi][nt][2];
                S[(cl + 1) * SPITCH + ol + 8] += acc[mi][nt][3];
            }
        }
        __syncthreads();

        const float4 gm = *(const float4*)&gamma[o0 + 4 * lane];
        const float4 bt = *(const float4*)&beta[o0 + 4 * lane];
        for (int j = 0; j < 16; ++j) {
            const int nl = warp * 16 + j;
            float4 v = *(float4*)&S[nl * SPITCH + 4 * lane];
            v.x = fmaxf(fmaf(v.x, gm.x * inv, bt.x), 0.0f);
            v.y = fmaxf(fmaf(v.y, gm.y * inv, bt.y), 0.0f);
            v.z = fmaxf(fmaf(v.z, gm.z * inv, bt.z), 0.0f);
            v.w = fmaxf(fmaf(v.w, gm.w * inv, bt.w), 0.0f);
            const size_t hb = ((size_t)bz * NPTS + n0 + nl) * CH + o0 + 4 * lane;
            *(__half2*)&g_Hf[hb]     = __floats2half2_rn(v.x, v.y);
            *(__half2*)&g_Hf[hb + 2] = __floats2half2_rn(v.z, v.w);
        }
        return;
    }

    // MODE 0 / 1: direct fragment stores (R9 layout)
    float* outB = Out + bz * oBS;
    #pragma unroll
    for (int mi = 0; mi < 2; ++mi) {
        const int r0 = blockIdx.y * 128 + wm * 32 + mi * 16 + (lane >> 2);
        #pragma unroll
        for (int nt = 0; nt < 8; ++nt) {
            const int c0 = blockIdx.x * 128 + wn * 64 + nt * 8 + (lane & 3) * 2;
            float v0 = acc[mi][nt][0], v1 = acc[mi][nt][1];
            float v2 = acc[mi][nt][2], v3 = acc[mi][nt][3];
            if (MODE == 1) {
                const float s0 = __ldg(&gamma[c0])     * inv;
                const float s1 = __ldg(&gamma[c0 + 1]) * inv;
                const float b0 = __ldg(&beta[c0]);
                const float b1 = __ldg(&beta[c0 + 1]);
                v0 = fmaxf(fmaf(v0, s0, b0), 0.0f);
                v1 = fmaxf(fmaf(v1, s1, b1), 0.0f);
                v2 = fmaxf(fmaf(v2, s0, b0), 0.0f);
                v3 = fmaxf(fmaf(v3, s1, b1), 0.0f);
            }
            outB[(size_t)c0       * outLd + r0]     = v0;
            outB[(size_t)(c0 + 1) * outLd + r0]     = v1;
            outB[(size_t)c0       * outLd + r0 + 8] = v2;
            outB[(size_t)(c0 + 1) * outLd + r0 + 8] = v3;
        }
    }
}

// ---------------------------------------------------------------------------
extern "C" void kernel_launch(void* const* d_in, const int* in_sizes, int n_in,
                              void* d_out, int out_size)
{
    const float* xyz1   = (const float*)d_in[0];
    const float* xyz2   = (const float*)d_in[1];
    const float* feat1  = (const float*)d_in[2];
    const float* feat2  = (const float*)d_in[3];
    const float* w1     = (const float*)d_in[4];
    const float* gamma1 = (const float*)d_in[5];
    const float* beta1  = (const float*)d_in[6];
    const float* w2     = (const float*)d_in[7];
    const float* gamma2 = (const float*)d_in[8];
    const float* beta2  = (const float*)d_in[9];
    float* out = (float*)d_out;

    float *Gp;
    __half *X1f, *X2f, *Hf, *W1ah, *W1al, *W1bh, *W1bl, *W2h, *W2l;
    cudaGetSymbolAddress((void**)&Gp,   g_G);
    cudaGetSymbolAddress((void**)&X1f,  g_X1f);
    cudaGetSymbolAddress((void**)&X2f,  g_X2f);
    cudaGetSymbolAddress((void**)&Hf,   g_Hf);
    cudaGetSymbolAddress((void**)&W1ah, g_W1ahi); cudaGetSymbolAddress((void**)&W1al, g_W1alo);
    cudaGetSymbolAddress((void**)&W1bh, g_W1bhi); cudaGetSymbolAddress((void**)&W1bl, g_W1blo);
    cudaGetSymbolAddress((void**)&W2h,  g_W2hi);  cudaGetSymbolAddress((void**)&W2l,  g_W2lo);

    cudaFuncSetAttribute(mma_gemm<0,1>, cudaFuncAttributeMaxDynamicSharedMemorySize, SMEM_GEMM);
    cudaFuncSetAttribute(mma_gemm<2,1>, cudaFuncAttributeMaxDynamicSharedMemorySize, SMEM_GEMM);
    cudaFuncSetAttribute(mma_gemm<1,0>, cudaFuncAttributeMaxDynamicSharedMemorySize, SMEM_GEMM);

    // 1. merged prep: kNN + weight splits + feature transposes
    prep_kernel<<<PREP_TOTAL, 256>>>(xyz1, xyz2, feat1, feat2, w1, w2);

    // 2. G[b][m][o] = W1a @ feat2   (A = W1a hi/lo, B = X2 single)
    mma_gemm<0,1><<<dim3(MPTS / 128, CH / 128, BB), 256, SMEM_GEMM>>>(
        W1ah, W1al, 0, X2f, nullptr, (size_t)MPTS * CH,
        Gp, (size_t)MPTS * CH, CH, nullptr, nullptr);

    // 3. F GEMM fused with interpolation/BN/ReLU -> g_Hf
    mma_gemm<2,1><<<dim3(NPTS / 128, CH / 128, BB), 256, SMEM_GEMM>>>(
        W1bh, W1bl, 0, X1f, nullptr, (size_t)NPTS * CH,
        nullptr, 0, 0, gamma1, beta1);

    // 4. Out[b][o][n] = relu(bn(W2 @ H))   (A = H single, B = W2 hi/lo)
    mma_gemm<1,0><<<dim3(CH / 128, NPTS / 128, BB), 256, SMEM_GEMM>>>(
        Hf, nullptr, (size_t)NPTS * CH, W2h, W2l, 0,
        out, (size_t)CH * NPTS, NPTS, gamma2, beta2);

    (void)in_sizes; (void)n_in; (void)out_size;
}

// round 13
// speedup vs baseline: 1.5970x; 1.1852x over previous
#include <cuda_runtime.h>
#include <cuda_fp16.h>
#include <cstdint>
#include <math.h>

#define BB   16
#define NPTS 4096
#define MPTS 1024
#define CH   256     // C1 = C2 = H1 = H2
#define LDW1 512     // w1 row stride (Cin)

// ---------------------------------------------------------------------------
// Scratch (static device globals)
// ---------------------------------------------------------------------------
__device__ int     g_idx[BB * NPTS * 3];
__device__ float   g_wts[BB * NPTS * 3];
__device__ float   g_G[BB * MPTS * CH];        // [b][m][o] fp32
__device__ __half  g_Hf[BB * NPTS * CH];       // [b][n][k] fp16
__device__ __half  g_X1f[BB * NPTS * CH];      // feat1^T  [b][n][k] fp16
__device__ __half  g_X2f[BB * MPTS * CH];      // feat2^T  [b][m][k] fp16
__device__ __half  g_W1af[CH * CH];            // fp16 weights (single)
__device__ __half  g_W1bf[CH * CH];
__device__ __half  g_W2f[CH * CH];

// ---------------------------------------------------------------------------
// PTX helpers (sm_80-baseline features only — valid on plain sm_100)
// ---------------------------------------------------------------------------
__device__ __forceinline__ uint32_t smem_u32(const void* p) {
    uint32_t a;
    asm("{ .reg .u64 t; cvta.to.shared.u64 t, %1; cvt.u32.u64 %0, t; }"
        : "=r"(a) : "l"(p));
    return a;
}
__device__ __forceinline__ void cp_async16(uint32_t saddr, const void* g) {
    asm volatile("cp.async.cg.shared.global [%0], [%1], 16;"
                 :: "r"(saddr), "l"(g) : "memory");
}
__device__ __forceinline__ void cp_commit() {
    asm volatile("cp.async.commit_group;" ::: "memory");
}
__device__ __forceinline__ void cp_wait1() {
    asm volatile("cp.async.wait_group 1;" ::: "memory");
}
__device__ __forceinline__ void ldm_x4(uint32_t* r, uint32_t addr) {
    asm volatile("ldmatrix.sync.aligned.m8n8.x4.shared.b16 {%0,%1,%2,%3}, [%4];"
                 : "=r"(r[0]), "=r"(r[1]), "=r"(r[2]), "=r"(r[3]) : "r"(addr));
}
__device__ __forceinline__ void mma_f16(float* d, const uint32_t* a, const uint32_t* b) {
    asm volatile(
        "mma.sync.aligned.m16n8k16.row.col.f32.f16.f16.f32 "
        "{%0,%1,%2,%3}, {%4,%5,%6,%7}, {%8,%9}, {%0,%1,%2,%3};"
        : "+f"(d[0]), "+f"(d[1]), "+f"(d[2]), "+f"(d[3])
        : "r"(a[0]), "r"(a[1]), "r"(a[2]), "r"(a[3]), "r"(b[0]), "r"(b[1]));
}

// ---------------------------------------------------------------------------
// Kernel A: merged prep — kNN + 3 weight fp16 converts + 2 feature transposes.
// ---------------------------------------------------------------------------
#define PREP_KNN_BLKS    256
#define PREP_W_BLKS      768
#define PREP_T2_BLKS     4096
#define PREP_TOTAL       (PREP_KNN_BLKS + PREP_W_BLKS + PREP_T2_BLKS + 16384)

__device__ __forceinline__ void do_transpose_f16(
    const float* __restrict__ Xb, int nn, int n0, int k0,
    __half* __restrict__ T, float (*s)[33], int tx, int ty)
{
    #pragma unroll
    for (int j = 0; j < 4; ++j) {
        const int kl = ty + j * 8;
        s[kl][tx] = Xb[(size_t)(k0 + kl) * nn + n0 + tx];
    }
    __syncthreads();
    #pragma unroll
    for (int j = 0; j < 4; ++j) {
        const int nl = ty + j * 8;
        T[(size_t)(n0 + nl) * CH + k0 + tx] = __float2half(s[tx][nl]);
    }
}

__global__ __launch_bounds__(256)
void prep_kernel(const float* __restrict__ xyz1,  const float* __restrict__ xyz2,
                 const float* __restrict__ feat1, const float* __restrict__ feat2,
                 const float* __restrict__ w1,    const float* __restrict__ w2)
{
    __shared__ char smbuf[MPTS * 16];
    const int bid = blockIdx.x;
    const int t   = threadIdx.x;

    if (bid < PREP_KNN_BLKS) {
        float4* s4 = (float4*)smbuf;
        const int b = bid >> 4;
        const int g = bid & 15;

        for (int m = t; m < MPTS; m += 256) {
            const float* q = xyz2 + ((size_t)b * MPTS + m) * 3;
            const float x = q[0], y = q[1], z = q[2];
            s4[m] = make_float4(x, y, z, x * x + y * y + z * z);
        }
        __syncthreads();

        const int n = g * 256 + t;
        const float* p = xyz1 + ((size_t)b * NPTS + n) * 3;
        const float px = p[0], py = p[1], pz = p[2];
        const float qx2 = -2.0f * px, qy2 = -2.0f * py, qz2 = -2.0f * pz;
        const float qsq = px * px + py * py + pz * pz;

        float d0 = 3.4e38f, d1 = 3.4e38f, d2 = 3.4e38f;
        int   i0 = 0, i1 = 0, i2 = 0;

        #pragma unroll 4
        for (int m = 0; m < MPTS; ++m) {
            const float4 v = s4[m];
            float d = v.w;
            d = fmaf(qx2, v.x, d);
            d = fmaf(qy2, v.y, d);
            d = fmaf(qz2, v.z, d);
            if (d < d2) {
                if (d < d0)      { d2 = d1; i2 = i1; d1 = d0; i1 = i0; d0 = d; i0 = m; }
                else if (d < d1) { d2 = d1; i2 = i1; d1 = d;  i1 = m; }
                else             { d2 = d;  i2 = m; }
            }
        }

        d0 += qsq; d1 += qsq; d2 += qsq;
        const float wa = 1.0f / (d0 + 1e-8f);
        const float wb = 1.0f / (d1 + 1e-8f);
        const float wc = 1.0f / (d2 + 1e-8f);
        const float ws = 1.0f / (wa + wb + wc);

        const size_t o = ((size_t)b * NPTS + n) * 3;
        g_idx[o + 0] = i0; g_idx[o + 1] = i1; g_idx[o + 2] = i2;
        g_wts[o + 0] = wa * ws; g_wts[o + 1] = wb * ws; g_wts[o + 2] = wc * ws;
        return;
    }

    float (*s)[33] = (float (*)[33])smbuf;

    if (bid < PREP_KNN_BLKS + PREP_W_BLKS) {
        const int local = bid - PREP_KNN_BLKS;
        const int which = local >> 8;
        const int idx   = (local & 255) * 256 + t;
        const int o = idx >> 8, k = idx & 255;
        if (which == 0)      g_W1af[idx] = __float2half(w1[(size_t)o * LDW1 + k]);
        else if (which == 1) g_W1bf[idx] = __float2half(w1[(size_t)o * LDW1 + 256 + k]);
        else                 g_W2f[idx]  = __float2half(w2[(size_t)o * CH + k]);
    } else if (bid < PREP_KNN_BLKS + PREP_W_BLKS + PREP_T2_BLKS) {
        const int local = bid - PREP_KNN_BLKS - PREP_W_BLKS;
        const int n0 = (local & 31) * 32;
        const int k0 = ((local >> 5) & 7) * 32;
        const int b  = local >> 8;
        do_transpose_f16(feat2 + (size_t)b * CH * MPTS, MPTS, n0, k0,
                         g_X2f + (size_t)b * MPTS * CH, s, t & 31, t >> 5);
    } else {
        const int local = bid - PREP_KNN_BLKS - PREP_W_BLKS - PREP_T2_BLKS;
        const int n0 = (local & 127) * 32;
        const int k0 = ((local >> 7) & 7) * 32;
        const int b  = local >> 10;
        do_transpose_f16(feat1 + (size_t)b * CH * NPTS, NPTS, n0, k0,
                         g_X1f + (size_t)b * NPTS * CH, s, t & 31, t >> 5);
    }
}

// ---------------------------------------------------------------------------
// Tensor-core GEMM, plain fp16 x fp16, single mma term.
//   D[row][col] = sum_k A[row][k]*B[col][k], fp32 accum.
//   2 smem arrays/stage, XOR swizzle, 3-stage cp.async pipeline.
//   MODE 0: plain fp32 store        MODE 1: BN+ReLU fp32 store
//   MODE 2: interp-add + BN + ReLU -> fp16 H (gather-then-add, high MLP)
// ---------------------------------------------------------------------------
#define KTOT    256
#define KC      32
#define NCHUNK  (KTOT / KC)
#define ARR_B   (128 * 64)               // 8192 (128 rows x 32 fp16)
#define STAGE_B (2 * ARR_B)              // 16384
#define NSTAGE  3
#define SMEM_GEMM 69632                  // >= max(3*STAGE_B=49152, S=67584)
#define SPITCH  132

__device__ __forceinline__ uint32_t swz(int row, int chunk) {
    return (uint32_t)(row * 64 + ((chunk ^ ((row >> 1) & 3)) << 4));
}

template<int MODE>
__global__ __launch_bounds__(256, 2)
void mma_gemm(const __half* __restrict__ A, size_t aBS, int aPerB,
              const __half* __restrict__ B, size_t bBS, int bPerB,
              float* __restrict__ Out, size_t oBS, int outLd,
              const float* __restrict__ gamma, const float* __restrict__ beta)
{
    extern __shared__ char sm[];
    const uint32_t sb = smem_u32(sm);

    const int tid  = threadIdx.x;
    const int warp = tid >> 5;
    const int lane = tid & 31;
    const int wm   = warp & 3;           // 4 warps over A-rows
    const int wn   = warp >> 2;          // 2 warps over B-cols
    const int bz   = blockIdx.z;

    const __half* srcs[2] = {
        A + (aPerB ? bz * aBS : 0) + (size_t)(blockIdx.y * 128) * KTOT,
        B + (bPerB ? bz * bBS : 0) + (size_t)(blockIdx.x * 128) * KTOT };

    auto load_stage = [&](int c) {
        const int k0 = c * KC;
        const uint32_t stage = sb + (c % NSTAGE) * STAGE_B;
        #pragma unroll
        for (int i = 0; i < 4; ++i) {           // 1024 chunks, 4/thread
            const int id  = tid + i * 256;
            const int arr = id >> 9;
            const int id9 = id & 511;
            const int row = id9 >> 2;
            const int ch  = id9 & 3;
            cp_async16(stage + arr * ARR_B + swz(row, ch),
                       srcs[arr] + (size_t)row * KTOT + k0 + ch * 8);
        }
        cp_commit();
    };

    float acc[2][8][4];
    #pragma unroll
    for (int a = 0; a < 2; ++a)
        #pragma unroll
        for (int b = 0; b < 8; ++b)
            #pragma unroll
            for (int d = 0; d < 4; ++d) acc[a][b][d] = 0.0f;

    load_stage(0);
    load_stage(1);

    for (int c = 0; c < NCHUNK; ++c) {
        cp_wait1();
        __syncthreads();
        if (c + 2 < NCHUNK) load_stage(c + 2);
        else                cp_commit();

        const uint32_t stage = sb + (c % NSTAGE) * STAGE_B;
        const uint32_t aB = stage;
        const uint32_t bB = stage + ARR_B;

        #pragma unroll
        for (int s = 0; s < 2; ++s) {
            const int arow  = wm * 32 + (lane & 15);
            const int achnk = s * 2 + ((lane >> 4) & 1);
            const int brow  = wn * 64 + ((lane >> 4) << 3) + (lane & 7);
            const int bchnk = s * 2 + ((lane >> 3) & 1);

            uint32_t av[2][4];
            ldm_x4(av[0], aB + swz(arow,      achnk));
            ldm_x4(av[1], aB + swz(arow + 16, achnk));
            #pragma unroll
            for (int nt = 0; nt < 4; ++nt) {
                uint32_t bv[4];
                ldm_x4(bv, bB + swz(brow + nt * 16, bchnk));
                mma_f16(acc[0][2*nt],   av[0], bv);
                mma_f16(acc[1][2*nt],   av[1], bv);
                mma_f16(acc[0][2*nt+1], av[0], bv + 2);
                mma_f16(acc[1][2*nt+1], av[1], bv + 2);
            }
        }
    }

    const float inv = 1.0f / sqrtf(1.0f + 1e-5f);

    if (MODE == 2) {
        // gather interp -> S (high MLP), add acc, BN+ReLU, fp16 store
        __syncthreads();                 // pipeline smem dead; reuse as S
        float* S = (float*)sm;           // [128 n][SPITCH]
        const int n0 = blockIdx.x * 128;
        const int o0 = blockIdx.y * 128;
        const float* Gb = g_G + (size_t)bz * MPTS * CH;

        for (int j = 0; j < 16; ++j) {
            const int nl = warp * 16 + j;
            const size_t pb = (size_t)bz * NPTS + n0 + nl;
            const int   i0 = g_idx[pb * 3 + 0];
            const int   i1 = g_idx[pb * 3 + 1];
            const int   i2 = g_idx[pb * 3 + 2];
            const float w0 = g_wts[pb * 3 + 0];
            const float w1 = g_wts[pb * 3 + 1];
            const float w2 = g_wts[pb * 3 + 2];
            const float4 a4 = *(const float4*)(Gb + (size_t)i0 * CH + o0 + 4 * lane);
            const float4 b4 = *(const float4*)(Gb + (size_t)i1 * CH + o0 + 4 * lane);
            const float4 c4 = *(const float4*)(Gb + (size_t)i2 * CH + o0 + 4 * lane);
            float4 v;
            v.x = w0 * a4.x + w1 * b4.x + w2 * c4.x;
            v.y = w0 * a4.y + w1 * b4.y + w2 * c4.y;
            v.z = w0 * a4.z + w1 * b4.z + w2 * c4.z;
            v.w = w0 * a4.w + w1 * b4.w + w2 * c4.w;
            *(float4*)&S[nl * SPITCH + 4 * lane] = v;
        }
        __syncthreads();

        #pragma unroll
        for (int mi = 0; mi < 2; ++mi) {
            const int ol = wm * 32 + mi * 16 + (lane >> 2);
            #pragma unroll
            for (int nt = 0; nt < 8; ++nt) {
                const int cl = wn * 64 + nt * 8 + (lane & 3) * 2;
                S[cl * SPITCH + ol]           += acc[mi][nt][0];
                S[(cl + 1) * SPITCH + ol]     += acc[mi][nt][1];
                S[cl * SPITCH + ol + 8]       += acc[mi][nt][2];
                S[(cl + 1) * SPITCH + ol + 8] += acc[mi][nt][3];
            }
        }
        __syncthreads();

        const float4 gm = *(const float4*)&gamma[o0 + 4 * lane];
        const float4 bt = *(const float4*)&beta[o0 + 4 * lane];
        for (int j = 0; j < 16; ++j) {
            const int nl = warp * 16 + j;
            float4 v = *(float4*)&S[nl * SPITCH + 4 * lane];
            v.x = fmaxf(fmaf(v.x, gm.x * inv, bt.x), 0.0f);
            v.y = fmaxf(fmaf(v.y, gm.y * inv, bt.y), 0.0f);
            v.z = fmaxf(fmaf(v.z, gm.z * inv, bt.z), 0.0f);
            v.w = fmaxf(fmaf(v.w, gm.w * inv, bt.w), 0.0f);
            const size_t hb = ((size_t)bz * NPTS + n0 + nl) * CH + o0 + 4 * lane;
            *(__half2*)&g_Hf[hb]     = __floats2half2_rn(v.x, v.y);
            *(__half2*)&g_Hf[hb + 2] = __floats2half2_rn(v.z, v.w);
        }
        return;
    }

    // MODE 0 / 1: direct fragment stores
    float* outB = Out + bz * oBS;
    #pragma unroll
    for (int mi = 0; mi < 2; ++mi) {
        const int r0 = blockIdx.y * 128 + wm * 32 + mi * 16 + (lane >> 2);
        #pragma unroll
        for (int nt = 0; nt < 8; ++nt) {
            const int c0 = blockIdx.x * 128 + wn * 64 + nt * 8 + (lane & 3) * 2;
            float v0 = acc[mi][nt][0], v1 = acc[mi][nt][1];
            float v2 = acc[mi][nt][2], v3 = acc[mi][nt][3];
            if (MODE == 1) {
                const float s0 = __ldg(&gamma[c0])     * inv;
                const float s1 = __ldg(&gamma[c0 + 1]) * inv;
                const float b0 = __ldg(&beta[c0]);
                const float b1 = __ldg(&beta[c0 + 1]);
                v0 = fmaxf(fmaf(v0, s0, b0), 0.0f);
                v1 = fmaxf(fmaf(v1, s1, b1), 0.0f);
                v2 = fmaxf(fmaf(v2, s0, b0), 0.0f);
                v3 = fmaxf(fmaf(v3, s1, b1), 0.0f);
            }
            outB[(size_t)c0       * outLd + r0]     = v0;
            outB[(size_t)(c0 + 1) * outLd + r0]     = v1;
            outB[(size_t)c0       * outLd + r0 + 8] = v2;
            outB[(size_t)(c0 + 1) * outLd + r0 + 8] = v3;
        }
    }
}

// ---------------------------------------------------------------------------
extern "C" void kernel_launch(void* const* d_in, const int* in_sizes, int n_in,
                              void* d_out, int out_size)
{
    const float* xyz1   = (const float*)d_in[0];
    const float* xyz2   = (const float*)d_in[1];
    const float* feat1  = (const float*)d_in[2];
    const float* feat2  = (const float*)d_in[3];
    const float* w1     = (const float*)d_in[4];
    const float* gamma1 = (const float*)d_in[5];
    const float* beta1  = (const float*)d_in[6];
    const float* w2     = (const float*)d_in[7];
    const float* gamma2 = (const float*)d_in[8];
    const float* beta2  = (const float*)d_in[9];
    float* out = (float*)d_out;

    float *Gp;
    __half *X1f, *X2f, *Hf, *W1af, *W1bf, *W2f;
    cudaGetSymbolAddress((void**)&Gp,   g_G);
    cudaGetSymbolAddress((void**)&X1f,  g_X1f);
    cudaGetSymbolAddress((void**)&X2f,  g_X2f);
    cudaGetSymbolAddress((void**)&Hf,   g_Hf);
    cudaGetSymbolAddress((void**)&W1af, g_W1af);
    cudaGetSymbolAddress((void**)&W1bf, g_W1bf);
    cudaGetSymbolAddress((void**)&W2f,  g_W2f);

    cudaFuncSetAttribute(mma_gemm<0>, cudaFuncAttributeMaxDynamicSharedMemorySize, SMEM_GEMM);
    cudaFuncSetAttribute(mma_gemm<1>, cudaFuncAttributeMaxDynamicSharedMemorySize, SMEM_GEMM);
    cudaFuncSetAttribute(mma_gemm<2>, cudaFuncAttributeMaxDynamicSharedMemorySize, SMEM_GEMM);

    // 1. merged prep: kNN + weight converts + feature transposes
    prep_kernel<<<PREP_TOTAL, 256>>>(xyz1, xyz2, feat1, feat2, w1, w2);

    // 2. G[b][m][o] = W1a @ feat2   (A = W1a, B = X2)
    mma_gemm<0><<<dim3(MPTS / 128, CH / 128, BB), 256, SMEM_GEMM>>>(
        W1af, 0, 0, X2f, (size_t)MPTS * CH, 1,
        Gp, (size_t)MPTS * CH, CH, nullptr, nullptr);

    // 3. F GEMM fused with interpolation/BN/ReLU -> g_Hf
    mma_gemm<2><<<dim3(NPTS / 128, CH / 128, BB), 256, SMEM_GEMM>>>(
        W1bf, 0, 0, X1f, (size_t)NPTS * CH, 1,
        nullptr, 0, 0, gamma1, beta1);

    // 4. Out[b][o][n] = relu(bn(W2 @ H))   (A = H, B = W2)
    mma_gemm<1><<<dim3(CH / 128, NPTS / 128, BB), 256, SMEM_GEMM>>>(
        Hf, (size_t)NPTS * CH, 1, W2f, 0, 0,
        out, (size_t)CH * NPTS, NPTS, gamma2, beta2);

    (void)in_sizes; (void)n_in; (void)out_size;
}

// round 14
// speedup vs baseline: 1.6077x; 1.0067x over previous
#include <cuda_runtime.h>
#include <cuda_fp16.h>
#include <cstdint>
#include <math.h>

#define BB   16
#define NPTS 4096
#define MPTS 1024
#define CH   256     // C1 = C2 = H1 = H2
#define LDW1 512     // w1 row stride (Cin)

// ---------------------------------------------------------------------------
// Scratch (static device globals)
// ---------------------------------------------------------------------------
__device__ int     g_idx[BB * NPTS * 3];
__device__ float   g_wts[BB * NPTS * 3];
__device__ __half  g_Gh[BB * MPTS * CH];       // [b][m][o] fp16
__device__ __half  g_Hf[BB * NPTS * CH];       // [b][n][k] fp16
__device__ __half  g_X1f[BB * NPTS * CH];      // feat1^T  [b][n][k] fp16
__device__ __half  g_X2f[BB * MPTS * CH];      // feat2^T  [b][m][k] fp16
__device__ __half  g_W1af[CH * CH];            // fp16 weights (single)
__device__ __half  g_W1bf[CH * CH];
__device__ __half  g_W2f[CH * CH];

// ---------------------------------------------------------------------------
// PTX helpers (sm_80-baseline features only — valid on plain sm_100)
// ---------------------------------------------------------------------------
__device__ __forceinline__ uint32_t smem_u32(const void* p) {
    uint32_t a;
    asm("{ .reg .u64 t; cvta.to.shared.u64 t, %1; cvt.u32.u64 %0, t; }"
        : "=r"(a) : "l"(p));
    return a;
}
__device__ __forceinline__ void cp_async16(uint32_t saddr, const void* g) {
    asm volatile("cp.async.cg.shared.global [%0], [%1], 16;"
                 :: "r"(saddr), "l"(g) : "memory");
}
__device__ __forceinline__ void cp_commit() {
    asm volatile("cp.async.commit_group;" ::: "memory");
}
__device__ __forceinline__ void cp_wait1() {
    asm volatile("cp.async.wait_group 1;" ::: "memory");
}
__device__ __forceinline__ void ldm_x4(uint32_t* r, uint32_t addr) {
    asm volatile("ldmatrix.sync.aligned.m8n8.x4.shared.b16 {%0,%1,%2,%3}, [%4];"
                 : "=r"(r[0]), "=r"(r[1]), "=r"(r[2]), "=r"(r[3]) : "r"(addr));
}
__device__ __forceinline__ void mma_f16(float* d, const uint32_t* a, const uint32_t* b) {
    asm volatile(
        "mma.sync.aligned.m16n8k16.row.col.f32.f16.f16.f32 "
        "{%0,%1,%2,%3}, {%4,%5,%6,%7}, {%8,%9}, {%0,%1,%2,%3};"
        : "+f"(d[0]), "+f"(d[1]), "+f"(d[2]), "+f"(d[3])
        : "r"(a[0]), "r"(a[1]), "r"(a[2]), "r"(a[3]), "r"(b[0]), "r"(b[1]));
}

// ---------------------------------------------------------------------------
// Kernel A: merged prep — kNN + 3 weight fp16 converts + 2 feature transposes.
// ---------------------------------------------------------------------------
#define PREP_KNN_BLKS    256
#define PREP_W_BLKS      768
#define PREP_T2_BLKS     4096
#define PREP_TOTAL       (PREP_KNN_BLKS + PREP_W_BLKS + PREP_T2_BLKS + 16384)

__device__ __forceinline__ void do_transpose_f16(
    const float* __restrict__ Xb, int nn, int n0, int k0,
    __half* __restrict__ T, float (*s)[33], int tx, int ty)
{
    #pragma unroll
    for (int j = 0; j < 4; ++j) {
        const int kl = ty + j * 8;
        s[kl][tx] = Xb[(size_t)(k0 + kl) * nn + n0 + tx];
    }
    __syncthreads();
    #pragma unroll
    for (int j = 0; j < 4; ++j) {
        const int nl = ty + j * 8;
        T[(size_t)(n0 + nl) * CH + k0 + tx] = __float2half(s[tx][nl]);
    }
}

__global__ __launch_bounds__(256)
void prep_kernel(const float* __restrict__ xyz1,  const float* __restrict__ xyz2,
                 const float* __restrict__ feat1, const float* __restrict__ feat2,
                 const float* __restrict__ w1,    const float* __restrict__ w2)
{
    __shared__ char smbuf[MPTS * 16];
    const int bid = blockIdx.x;
    const int t   = threadIdx.x;

    if (bid < PREP_KNN_BLKS) {
        float4* s4 = (float4*)smbuf;
        const int b = bid >> 4;
        const int g = bid & 15;

        for (int m = t; m < MPTS; m += 256) {
            const float* q = xyz2 + ((size_t)b * MPTS + m) * 3;
            const float x = q[0], y = q[1], z = q[2];
            s4[m] = make_float4(x, y, z, x * x + y * y + z * z);
        }
        __syncthreads();

        const int n = g * 256 + t;
        const float* p = xyz1 + ((size_t)b * NPTS + n) * 3;
        const float px = p[0], py = p[1], pz = p[2];
        const float qx2 = -2.0f * px, qy2 = -2.0f * py, qz2 = -2.0f * pz;
        const float qsq = px * px + py * py + pz * pz;

        float d0 = 3.4e38f, d1 = 3.4e38f, d2 = 3.4e38f;
        int   i0 = 0, i1 = 0, i2 = 0;

        #pragma unroll 4
        for (int m = 0; m < MPTS; ++m) {
            const float4 v = s4[m];
            float d = v.w;
            d = fmaf(qx2, v.x, d);
            d = fmaf(qy2, v.y, d);
            d = fmaf(qz2, v.z, d);
            if (d < d2) {
                if (d < d0)      { d2 = d1; i2 = i1; d1 = d0; i1 = i0; d0 = d; i0 = m; }
                else if (d < d1) { d2 = d1; i2 = i1; d1 = d;  i1 = m; }
                else             { d2 = d;  i2 = m; }
            }
        }

        d0 += qsq; d1 += qsq; d2 += qsq;
        const float wa = 1.0f / (d0 + 1e-8f);
        const float wb = 1.0f / (d1 + 1e-8f);
        const float wc = 1.0f / (d2 + 1e-8f);
        const float ws = 1.0f / (wa + wb + wc);

        const size_t o = ((size_t)b * NPTS + n) * 3;
        g_idx[o + 0] = i0; g_idx[o + 1] = i1; g_idx[o + 2] = i2;
        g_wts[o + 0] = wa * ws; g_wts[o + 1] = wb * ws; g_wts[o + 2] = wc * ws;
        return;
    }

    float (*s)[33] = (float (*)[33])smbuf;

    if (bid < PREP_KNN_BLKS + PREP_W_BLKS) {
        const int local = bid - PREP_KNN_BLKS;
        const int which = local >> 8;
        const int idx   = (local & 255) * 256 + t;
        const int o = idx >> 8, k = idx & 255;
        if (which == 0)      g_W1af[idx] = __float2half(w1[(size_t)o * LDW1 + k]);
        else if (which == 1) g_W1bf[idx] = __float2half(w1[(size_t)o * LDW1 + 256 + k]);
        else                 g_W2f[idx]  = __float2half(w2[(size_t)o * CH + k]);
    } else if (bid < PREP_KNN_BLKS + PREP_W_BLKS + PREP_T2_BLKS) {
        const int local = bid - PREP_KNN_BLKS - PREP_W_BLKS;
        const int n0 = (local & 31) * 32;
        const int k0 = ((local >> 5) & 7) * 32;
        const int b  = local >> 8;
        do_transpose_f16(feat2 + (size_t)b * CH * MPTS, MPTS, n0, k0,
                         g_X2f + (size_t)b * MPTS * CH, s, t & 31, t >> 5);
    } else {
        const int local = bid - PREP_KNN_BLKS - PREP_W_BLKS - PREP_T2_BLKS;
        const int n0 = (local & 127) * 32;
        const int k0 = ((local >> 7) & 7) * 32;
        const int b  = local >> 10;
        do_transpose_f16(feat1 + (size_t)b * CH * NPTS, NPTS, n0, k0,
                         g_X1f + (size_t)b * NPTS * CH, s, t & 31, t >> 5);
    }
}

// ---------------------------------------------------------------------------
// Tensor-core GEMM, plain fp16 x fp16, single mma term.
//   KC=64 (4 k16 steps/chunk, half the syncs), SW128 swizzle, 3-stage pipeline.
//   MODE 0: fp16 store -> g_Gh             (G GEMM)
//   MODE 1: BN+ReLU fp32 store -> Out      (GEMM2)
//   MODE 2: interp-add(fp16 G) + BN + ReLU -> fp16 H   (F GEMM)
// ---------------------------------------------------------------------------
#define KTOT    256
#define KC      64
#define NCHUNK  (KTOT / KC)              // 4
#define ARR_B   (128 * 128)              // 16384 (128 rows x 64 fp16 = 128B)
#define STAGE_B (2 * ARR_B)              // 32768
#define NSTAGE  3
#define SMEM_GEMM (NSTAGE * STAGE_B)     // 98304 (>= S = 67584)
#define SPITCH  132

// SW128: 16B-chunk 0..7 within a 128B row; ch ^= row&7
__device__ __forceinline__ uint32_t swz(int row, int ch) {
    return (uint32_t)(row * 128 + ((ch ^ (row & 7)) << 4));
}

template<int MODE>
__global__ __launch_bounds__(256, 2)
void mma_gemm(const __half* __restrict__ A, size_t aBS, int aPerB,
              const __half* __restrict__ B, size_t bBS, int bPerB,
              float* __restrict__ Out, size_t oBS, int outLd,
              const float* __restrict__ gamma, const float* __restrict__ beta)
{
    extern __shared__ char sm[];
    const uint32_t sb = smem_u32(sm);

    const int tid  = threadIdx.x;
    const int warp = tid >> 5;
    const int lane = tid & 31;
    const int wm   = warp & 3;           // 4 warps over A-rows
    const int wn   = warp >> 2;          // 2 warps over B-cols
    const int bz   = blockIdx.z;

    const __half* srcs[2] = {
        A + (aPerB ? bz * aBS : 0) + (size_t)(blockIdx.y * 128) * KTOT,
        B + (bPerB ? bz * bBS : 0) + (size_t)(blockIdx.x * 128) * KTOT };

    auto load_stage = [&](int c) {
        const int k0 = c * KC;
        const uint32_t stage = sb + (c % NSTAGE) * STAGE_B;
        #pragma unroll
        for (int i = 0; i < 8; ++i) {           // 2048 chunks, 8/thread
            const int id   = tid + i * 256;
            const int arr  = id >> 10;
            const int id10 = id & 1023;
            const int row  = id10 >> 3;
            const int ch   = id10 & 7;
            cp_async16(stage + arr * ARR_B + swz(row, ch),
                       srcs[arr] + (size_t)row * KTOT + k0 + ch * 8);
        }
        cp_commit();
    };

    float acc[2][8][4];
    #pragma unroll
    for (int a = 0; a < 2; ++a)
        #pragma unroll
        for (int b = 0; b < 8; ++b)
            #pragma unroll
            for (int d = 0; d < 4; ++d) acc[a][b][d] = 0.0f;

    load_stage(0);
    load_stage(1);

    for (int c = 0; c < NCHUNK; ++c) {
        cp_wait1();
        __syncthreads();
        if (c + 2 < NCHUNK) load_stage(c + 2);
        else                cp_commit();

        const uint32_t stage = sb + (c % NSTAGE) * STAGE_B;
        const uint32_t aB = stage;
        const uint32_t bB = stage + ARR_B;

        #pragma unroll
        for (int s = 0; s < 4; ++s) {           // 4 k16 steps per chunk
            const int arow  = wm * 32 + (lane & 15);
            const int achnk = s * 2 + ((lane >> 4) & 1);
            const int brow  = wn * 64 + ((lane >> 4) << 3) + (lane & 7);
            const int bchnk = s * 2 + ((lane >> 3) & 1);

            uint32_t av[2][4];
            ldm_x4(av[0], aB + swz(arow,      achnk));
            ldm_x4(av[1], aB + swz(arow + 16, achnk));
            #pragma unroll
            for (int nt = 0; nt < 4; ++nt) {
                uint32_t bv[4];
                ldm_x4(bv, bB + swz(brow + nt * 16, bchnk));
                mma_f16(acc[0][2*nt],   av[0], bv);
                mma_f16(acc[1][2*nt],   av[1], bv);
                mma_f16(acc[0][2*nt+1], av[0], bv + 2);
                mma_f16(acc[1][2*nt+1], av[1], bv + 2);
            }
        }
    }

    const float inv = 1.0f / sqrtf(1.0f + 1e-5f);

    if (MODE == 2) {
        // gather interp (fp16 G, high MLP) -> S, add acc, BN+ReLU, fp16 store
        __syncthreads();                 // pipeline smem dead; reuse as S
        float* S = (float*)sm;           // [128 n][SPITCH]
        const int n0 = blockIdx.x * 128;
        const int o0 = blockIdx.y * 128;
        const __half* Gb = g_Gh + (size_t)bz * MPTS * CH;

        for (int j = 0; j < 16; ++j) {
            const int nl = warp * 16 + j;
            const size_t pb = (size_t)bz * NPTS + n0 + nl;
            const int   i0 = g_idx[pb * 3 + 0];
            const int   i1 = g_idx[pb * 3 + 1];
            const int   i2 = g_idx[pb * 3 + 2];
            const float w0 = g_wts[pb * 3 + 0];
            const float w1 = g_wts[pb * 3 + 1];
            const float w2 = g_wts[pb * 3 + 2];
            const __half2* gr0 = (const __half2*)(Gb + (size_t)i0 * CH + o0 + 4 * lane);
            const __half2* gr1 = (const __half2*)(Gb + (size_t)i1 * CH + o0 + 4 * lane);
            const __half2* gr2 = (const __half2*)(Gb + (size_t)i2 * CH + o0 + 4 * lane);
            const float2 a0 = __half22float2(gr0[0]), a1 = __half22float2(gr0[1]);
            const float2 b0 = __half22float2(gr1[0]), b1 = __half22float2(gr1[1]);
            const float2 c0 = __half22float2(gr2[0]), c1 = __half22float2(gr2[1]);
            float4 v;
            v.x = w0 * a0.x + w1 * b0.x + w2 * c0.x;
            v.y = w0 * a0.y + w1 * b0.y + w2 * c0.y;
            v.z = w0 * a1.x + w1 * b1.x + w2 * c1.x;
            v.w = w0 * a1.y + w1 * b1.y + w2 * c1.y;
            *(float4*)&S[nl * SPITCH + 4 * lane] = v;
        }
        __syncthreads();

        #pragma unroll
        for (int mi = 0; mi < 2; ++mi) {
            const int ol = wm * 32 + mi * 16 + (lane >> 2);
            #pragma unroll
            for (int nt = 0; nt < 8; ++nt) {
                const int cl = wn * 64 + nt * 8 + (lane & 3) * 2;
                S[cl * SPITCH + ol]           += acc[mi][nt][0];
                S[(cl + 1) * SPITCH + ol]     += acc[mi][nt][1];
                S[cl * SPITCH + ol + 8]       += acc[mi][nt][2];
                S[(cl + 1) * SPITCH + ol + 8] += acc[mi][nt][3];
            }
        }
        __syncthreads();

        const float4 gm = *(const float4*)&gamma[o0 + 4 * lane];
        const float4 bt = *(const float4*)&beta[o0 + 4 * lane];
        for (int j = 0; j < 16; ++j) {
            const int nl = warp * 16 + j;
            float4 v = *(float4*)&S[nl * SPITCH + 4 * lane];
            v.x = fmaxf(fmaf(v.x, gm.x * inv, bt.x), 0.0f);
            v.y = fmaxf(fmaf(v.y, gm.y * inv, bt.y), 0.0f);
            v.z = fmaxf(fmaf(v.z, gm.z * inv, bt.z), 0.0f);
            v.w = fmaxf(fmaf(v.w, gm.w * inv, bt.w), 0.0f);
            const size_t hb = ((size_t)bz * NPTS + n0 + nl) * CH + o0 + 4 * lane;
            *(__half2*)&g_Hf[hb]     = __floats2half2_rn(v.x, v.y);
            *(__half2*)&g_Hf[hb + 2] = __floats2half2_rn(v.z, v.w);
        }
        return;
    }

    if (MODE == 0) {
        // fp16 store to g_Gh[m][o]  (cols = m, rows = o)
        __half* Gh = g_Gh + (size_t)bz * MPTS * CH;
        #pragma unroll
        for (int mi = 0; mi < 2; ++mi) {
            const int r0 = blockIdx.y * 128 + wm * 32 + mi * 16 + (lane >> 2);
            #pragma unroll
            for (int nt = 0; nt < 8; ++nt) {
                const int c0 = blockIdx.x * 128 + wn * 64 + nt * 8 + (lane & 3) * 2;
                Gh[(size_t)c0       * CH + r0]     = __float2half(acc[mi][nt][0]);
                Gh[(size_t)(c0 + 1) * CH + r0]     = __float2half(acc[mi][nt][1]);
                Gh[(size_t)c0       * CH + r0 + 8] = __float2half(acc[mi][nt][2]);
                Gh[(size_t)(c0 + 1) * CH + r0 + 8] = __float2half(acc[mi][nt][3]);
            }
        }
        return;
    }

    // MODE 1: BN+ReLU fp32 fragment stores
    float* outB = Out + bz * oBS;
    #pragma unroll
    for (int mi = 0; mi < 2; ++mi) {
        const int r0 = blockIdx.y * 128 + wm * 32 + mi * 16 + (lane >> 2);
        #pragma unroll
        for (int nt = 0; nt < 8; ++nt) {
            const int c0 = blockIdx.x * 128 + wn * 64 + nt * 8 + (lane & 3) * 2;
            float v0 = acc[mi][nt][0], v1 = acc[mi][nt][1];
            float v2 = acc[mi][nt][2], v3 = acc[mi][nt][3];
            const float s0 = __ldg(&gamma[c0])     * inv;
            const float s1 = __ldg(&gamma[c0 + 1]) * inv;
            const float b0 = __ldg(&beta[c0]);
            const float b1 = __ldg(&beta[c0 + 1]);
            v0 = fmaxf(fmaf(v0, s0, b0), 0.0f);
            v1 = fmaxf(fmaf(v1, s1, b1), 0.0f);
            v2 = fmaxf(fmaf(v2, s0, b0), 0.0f);
            v3 = fmaxf(fmaf(v3, s1, b1), 0.0f);
            outB[(size_t)c0       * outLd + r0]     = v0;
            outB[(size_t)(c0 + 1) * outLd + r0]     = v1;
            outB[(size_t)c0       * outLd + r0 + 8] = v2;
            outB[(size_t)(c0 + 1) * outLd + r0 + 8] = v3;
        }
    }
}

// ---------------------------------------------------------------------------
extern "C" void kernel_launch(void* const* d_in, const int* in_sizes, int n_in,
                              void* d_out, int out_size)
{
    const float* xyz1   = (const float*)d_in[0];
    const float* xyz2   = (const float*)d_in[1];
    const float* feat1  = (const float*)d_in[2];
    const float* feat2  = (const float*)d_in[3];
    const float* w1     = (const float*)d_in[4];
    const float* gamma1 = (const float*)d_in[5];
    const float* beta1  = (const float*)d_in[6];
    const float* w2     = (const float*)d_in[7];
    const float* gamma2 = (const float*)d_in[8];
    const float* beta2  = (const float*)d_in[9];
    float* out = (float*)d_out;

    __half *X1f, *X2f, *Hf, *W1af, *W1bf, *W2f;
    cudaGetSymbolAddress((void**)&X1f,  g_X1f);
    cudaGetSymbolAddress((void**)&X2f,  g_X2f);
    cudaGetSymbolAddress((void**)&Hf,   g_Hf);
    cudaGetSymbolAddress((void**)&W1af, g_W1af);
    cudaGetSymbolAddress((void**)&W1bf, g_W1bf);
    cudaGetSymbolAddress((void**)&W2f,  g_W2f);

    cudaFuncSetAttribute(mma_gemm<0>, cudaFuncAttributeMaxDynamicSharedMemorySize, SMEM_GEMM);
    cudaFuncSetAttribute(mma_gemm<1>, cudaFuncAttributeMaxDynamicSharedMemorySize, SMEM_GEMM);
    cudaFuncSetAttribute(mma_gemm<2>, cudaFuncAttributeMaxDynamicSharedMemorySize, SMEM_GEMM);

    // 1. merged prep: kNN + weight converts + feature transposes
    prep_kernel<<<PREP_TOTAL, 256>>>(xyz1, xyz2, feat1, feat2, w1, w2);

    // 2. G[b][m][o] = W1a @ feat2  -> fp16 g_Gh
    mma_gemm<0><<<dim3(MPTS / 128, CH / 128, BB), 256, SMEM_GEMM>>>(
        W1af, 0, 0, X2f, (size_t)MPTS * CH, 1,
        nullptr, 0, 0, nullptr, nullptr);

    // 3. F GEMM fused with interpolation/BN/ReLU -> g_Hf
    mma_gemm<2><<<dim3(NPTS / 128, CH / 128, BB), 256, SMEM_GEMM>>>(
        W1bf, 0, 0, X1f, (size_t)NPTS * CH, 1,
        nullptr, 0, 0, gamma1, beta1);

    // 4. Out[b][o][n] = relu(bn(W2 @ H))
    mma_gemm<1><<<dim3(CH / 128, NPTS / 128, BB), 256, SMEM_GEMM>>>(
        Hf, (size_t)NPTS * CH, 1, W2f, 0, 0,
        out, (size_t)CH * NPTS, NPTS, gamma2, beta2);

    (void)in_sizes; (void)n_in; (void)out_size;
}

// round 15
// speedup vs baseline: 1.6169x; 1.0057x over previous
#include <cuda_runtime.h>
#include <cuda_fp16.h>
#include <cstdint>
#include <math.h>

#define BB   16
#define NPTS 4096
#define MPTS 1024
#define CH   256     // C1 = C2 = H1 = H2
#define LDW1 512     // w1 row stride (Cin)

// ---------------------------------------------------------------------------
// Scratch (static device globals)
// ---------------------------------------------------------------------------
__device__ int     g_idx[BB * NPTS * 3];
__device__ float   g_wts[BB * NPTS * 3];
__device__ __half  g_Gh[BB * MPTS * CH];       // [b][m][o] fp16
__device__ __half  g_Hf[BB * NPTS * CH];       // [b][n][k] fp16
__device__ __half  g_X1f[BB * NPTS * CH];      // feat1^T  [b][n][k] fp16
__device__ __half  g_X2f[BB * MPTS * CH];      // feat2^T  [b][m][k] fp16
__device__ __half  g_W1af[CH * CH];            // fp16 weights
__device__ __half  g_W1bf[CH * CH];
__device__ __half  g_W2f[CH * CH];

// ---------------------------------------------------------------------------
// PTX helpers (sm_80-baseline features only — valid on plain sm_100)
// ---------------------------------------------------------------------------
__device__ __forceinline__ uint32_t smem_u32(const void* p) {
    uint32_t a;
    asm("{ .reg .u64 t; cvta.to.shared.u64 t, %1; cvt.u32.u64 %0, t; }"
        : "=r"(a) : "l"(p));
    return a;
}
__device__ __forceinline__ void cp_async16(uint32_t saddr, const void* g) {
    asm volatile("cp.async.cg.shared.global [%0], [%1], 16;"
                 :: "r"(saddr), "l"(g) : "memory");
}
__device__ __forceinline__ void cp_commit() {
    asm volatile("cp.async.commit_group;" ::: "memory");
}
__device__ __forceinline__ void cp_wait1() {
    asm volatile("cp.async.wait_group 1;" ::: "memory");
}
__device__ __forceinline__ void ldm_x4(uint32_t* r, uint32_t addr) {
    asm volatile("ldmatrix.sync.aligned.m8n8.x4.shared.b16 {%0,%1,%2,%3}, [%4];"
                 : "=r"(r[0]), "=r"(r[1]), "=r"(r[2]), "=r"(r[3]) : "r"(addr));
}
__device__ __forceinline__ void mma_f16(float* d, const uint32_t* a, const uint32_t* b) {
    asm volatile(
        "mma.sync.aligned.m16n8k16.row.col.f32.f16.f16.f32 "
        "{%0,%1,%2,%3}, {%4,%5,%6,%7}, {%8,%9}, {%0,%1,%2,%3};"
        : "+f"(d[0]), "+f"(d[1]), "+f"(d[2]), "+f"(d[3])
        : "r"(a[0]), "r"(a[1]), "r"(a[2]), "r"(a[3]), "r"(b[0]), "r"(b[1]));
}

// ---------------------------------------------------------------------------
// Kernel A: merged prep — kNN + 3 weight fp16 converts + 2 feature transposes.
//   Transpose tile: 32 n x 64 k; reads 128B/warp rows, writes 16B/thread.
// ---------------------------------------------------------------------------
#define PREP_KNN_BLKS    256
#define PREP_W_BLKS      768
#define PREP_T2_BLKS     2048            // (MPTS/32) * (CH/64) * BB = 32*4*16
#define PREP_T1_BLKS     8192            // (NPTS/32) * (CH/64) * BB = 128*4*16
#define PREP_TOTAL       (PREP_KNN_BLKS + PREP_W_BLKS + PREP_T2_BLKS + PREP_T1_BLKS)

__device__ __forceinline__ void do_transpose_f16(
    const float* __restrict__ Xb, int nn, int n0, int k0,
    __half* __restrict__ T, float (*s)[33], int t)
{
    const int tx = t & 31, ty = t >> 5;
    #pragma unroll
    for (int j = 0; j < 8; ++j) {
        const int kl = ty + j * 8;                 // 0..63
        s[kl][tx] = Xb[(size_t)(k0 + kl) * nn + n0 + tx];
    }
    __syncthreads();
    // write: thread -> one n row, 8 consecutive k as one 16B store
    const int nl = t >> 3;                         // 0..31
    const int kp = (t & 7) * 8;                    // 0..56
    __half h[8];
    #pragma unroll
    for (int q = 0; q < 8; ++q)
        h[q] = __float2half(s[kp + q][nl]);
    *(uint4*)&T[(size_t)(n0 + nl) * CH + k0 + kp] = *(uint4*)h;
}

__global__ __launch_bounds__(256)
void prep_kernel(const float* __restrict__ xyz1,  const float* __restrict__ xyz2,
                 const float* __restrict__ feat1, const float* __restrict__ feat2,
                 const float* __restrict__ w1,    const float* __restrict__ w2)
{
    __shared__ char smbuf[MPTS * 16];  // 16KB: float4[MPTS] / float[64][33]
    const int bid = blockIdx.x;
    const int t   = threadIdx.x;

    if (bid < PREP_KNN_BLKS) {
        float4* s4 = (float4*)smbuf;
        const int b = bid >> 4;
        const int g = bid & 15;

        for (int m = t; m < MPTS; m += 256) {
            const float* q = xyz2 + ((size_t)b * MPTS + m) * 3;
            const float x = q[0], y = q[1], z = q[2];
            s4[m] = make_float4(x, y, z, x * x + y * y + z * z);
        }
        __syncthreads();

        const int n = g * 256 + t;
        const float* p = xyz1 + ((size_t)b * NPTS + n) * 3;
        const float px = p[0], py = p[1], pz = p[2];
        const float qx2 = -2.0f * px, qy2 = -2.0f * py, qz2 = -2.0f * pz;
        const float qsq = px * px + py * py + pz * pz;

        float d0 = 3.4e38f, d1 = 3.4e38f, d2 = 3.4e38f;
        int   i0 = 0, i1 = 0, i2 = 0;

        #pragma unroll 4
        for (int m = 0; m < MPTS; ++m) {
            const float4 v = s4[m];
            float d = v.w;
            d = fmaf(qx2, v.x, d);
            d = fmaf(qy2, v.y, d);
            d = fmaf(qz2, v.z, d);
            if (d < d2) {
                if (d < d0)      { d2 = d1; i2 = i1; d1 = d0; i1 = i0; d0 = d; i0 = m; }
                else if (d < d1) { d2 = d1; i2 = i1; d1 = d;  i1 = m; }
                else             { d2 = d;  i2 = m; }
            }
        }

        d0 += qsq; d1 += qsq; d2 += qsq;
        const float wa = 1.0f / (d0 + 1e-8f);
        const float wb = 1.0f / (d1 + 1e-8f);
        const float wc = 1.0f / (d2 + 1e-8f);
        const float ws = 1.0f / (wa + wb + wc);

        const size_t o = ((size_t)b * NPTS + n) * 3;
        g_idx[o + 0] = i0; g_idx[o + 1] = i1; g_idx[o + 2] = i2;
        g_wts[o + 0] = wa * ws; g_wts[o + 1] = wb * ws; g_wts[o + 2] = wc * ws;
        return;
    }

    float (*s)[33] = (float (*)[33])smbuf;

    if (bid < PREP_KNN_BLKS + PREP_W_BLKS) {
        const int local = bid - PREP_KNN_BLKS;
        const int which = local >> 8;
        const int idx   = (local & 255) * 256 + t;
        const int o = idx >> 8, k = idx & 255;
        if (which == 0)      g_W1af[idx] = __float2half(w1[(size_t)o * LDW1 + k]);
        else if (which == 1) g_W1bf[idx] = __float2half(w1[(size_t)o * LDW1 + 256 + k]);
        else                 g_W2f[idx]  = __float2half(w2[(size_t)o * CH + k]);
    } else if (bid < PREP_KNN_BLKS + PREP_W_BLKS + PREP_T2_BLKS) {
        const int local = bid - PREP_KNN_BLKS - PREP_W_BLKS;
        const int n0 = (local & 31) * 32;              // MPTS/32 = 32
        const int k0 = ((local >> 5) & 3) * 64;        // CH/64 = 4
        const int b  = local >> 7;
        do_transpose_f16(feat2 + (size_t)b * CH * MPTS, MPTS, n0, k0,
                         g_X2f + (size_t)b * MPTS * CH, s, t);
    } else {
        const int local = bid - PREP_KNN_BLKS - PREP_W_BLKS - PREP_T2_BLKS;
        const int n0 = (local & 127) * 32;             // NPTS/32 = 128
        const int k0 = ((local >> 7) & 3) * 64;
        const int b  = local >> 9;
        do_transpose_f16(feat1 + (size_t)b * CH * NPTS, NPTS, n0, k0,
                         g_X1f + (size_t)b * NPTS * CH, s, t);
    }
}

// ---------------------------------------------------------------------------
// Tensor-core GEMM, plain fp16 x fp16, single mma term. KC=64, SW128 swizzle.
//   MODE 0: fp16 store staged via smem -> g_Gh (coalesced rows)   (G GEMM)
//   MODE 1: BN+ReLU fp32 fragment store -> Out                    (GEMM2)
//   MODE 2: interp-add(fp16 G) + BN + ReLU -> fp16 H              (F GEMM)
// ---------------------------------------------------------------------------
#define KTOT    256
#define KC      64
#define NCHUNK  (KTOT / KC)              // 4
#define ARR_B   (128 * 128)              // 16384 (128 rows x 64 fp16 = 128B)
#define STAGE_B (2 * ARR_B)              // 32768
#define NSTAGE  3
#define SMEM_GEMM (NSTAGE * STAGE_B)     // 98304 (>= S = 67584)
#define SPITCH  132

__device__ __forceinline__ uint32_t swz(int row, int ch) {
    return (uint32_t)(row * 128 + ((ch ^ (row & 7)) << 4));
}

template<int MODE>
__global__ __launch_bounds__(256, 2)
void mma_gemm(const __half* __restrict__ A, size_t aBS, int aPerB,
              const __half* __restrict__ B, size_t bBS, int bPerB,
              float* __restrict__ Out, size_t oBS, int outLd,
              const float* __restrict__ gamma, const float* __restrict__ beta)
{
    extern __shared__ char sm[];
    const uint32_t sb = smem_u32(sm);

    const int tid  = threadIdx.x;
    const int warp = tid >> 5;
    const int lane = tid & 31;
    const int wm   = warp & 3;
    const int wn   = warp >> 2;
    const int bz   = blockIdx.z;

    const __half* srcs[2] = {
        A + (aPerB ? bz * aBS : 0) + (size_t)(blockIdx.y * 128) * KTOT,
        B + (bPerB ? bz * bBS : 0) + (size_t)(blockIdx.x * 128) * KTOT };

    auto load_stage = [&](int c) {
        const int k0 = c * KC;
        const uint32_t stage = sb + (c % NSTAGE) * STAGE_B;
        #pragma unroll
        for (int i = 0; i < 8; ++i) {
            const int id   = tid + i * 256;
            const int arr  = id >> 10;
            const int id10 = id & 1023;
            const int row  = id10 >> 3;
            const int ch   = id10 & 7;
            cp_async16(stage + arr * ARR_B + swz(row, ch),
                       srcs[arr] + (size_t)row * KTOT + k0 + ch * 8);
        }
        cp_commit();
    };

    float acc[2][8][4];
    #pragma unroll
    for (int a = 0; a < 2; ++a)
        #pragma unroll
        for (int b = 0; b < 8; ++b)
            #pragma unroll
            for (int d = 0; d < 4; ++d) acc[a][b][d] = 0.0f;

    load_stage(0);
    load_stage(1);

    for (int c = 0; c < NCHUNK; ++c) {
        cp_wait1();
        __syncthreads();
        if (c + 2 < NCHUNK) load_stage(c + 2);
        else                cp_commit();

        const uint32_t stage = sb + (c % NSTAGE) * STAGE_B;
        const uint32_t aB = stage;
        const uint32_t bB = stage + ARR_B;

        #pragma unroll
        for (int s = 0; s < 4; ++s) {
            const int arow  = wm * 32 + (lane & 15);
            const int achnk = s * 2 + ((lane >> 4) & 1);
            const int brow  = wn * 64 + ((lane >> 4) << 3) + (lane & 7);
            const int bchnk = s * 2 + ((lane >> 3) & 1);

            uint32_t av[2][4];
            ldm_x4(av[0], aB + swz(arow,      achnk));
            ldm_x4(av[1], aB + swz(arow + 16, achnk));
            #pragma unroll
            for (int nt = 0; nt < 4; ++nt) {
                uint32_t bv[4];
                ldm_x4(bv, bB + swz(brow + nt * 16, bchnk));
                mma_f16(acc[0][2*nt],   av[0], bv);
                mma_f16(acc[1][2*nt],   av[1], bv);
                mma_f16(acc[0][2*nt+1], av[0], bv + 2);
                mma_f16(acc[1][2*nt+1], av[1], bv + 2);
            }
        }
    }

    const float inv = 1.0f / sqrtf(1.0f + 1e-5f);

    if (MODE == 2) {
        // gather interp (fp16 G, high MLP) -> S, add acc, BN+ReLU, fp16 store
        __syncthreads();
        float* S = (float*)sm;
        const int n0 = blockIdx.x * 128;
        const int o0 = blockIdx.y * 128;
        const __half* Gb = g_Gh + (size_t)bz * MPTS * CH;

        for (int j = 0; j < 16; ++j) {
            const int nl = warp * 16 + j;
            const size_t pb = (size_t)bz * NPTS + n0 + nl;
            const int   i0 = g_idx[pb * 3 + 0];
            const int   i1 = g_idx[pb * 3 + 1];
            const int   i2 = g_idx[pb * 3 + 2];
            const float w0 = g_wts[pb * 3 + 0];
            const float w1 = g_wts[pb * 3 + 1];
            const float w2 = g_wts[pb * 3 + 2];
            const __half2* gr0 = (const __half2*)(Gb + (size_t)i0 * CH + o0 + 4 * lane);
            const __half2* gr1 = (const __half2*)(Gb + (size_t)i1 * CH + o0 + 4 * lane);
            const __half2* gr2 = (const __half2*)(Gb + (size_t)i2 * CH + o0 + 4 * lane);
            const float2 a0 = __half22float2(gr0[0]), a1 = __half22float2(gr0[1]);
            const float2 b0 = __half22float2(gr1[0]), b1 = __half22float2(gr1[1]);
            const float2 c0 = __half22float2(gr2[0]), c1 = __half22float2(gr2[1]);
            float4 v;
            v.x = w0 * a0.x + w1 * b0.x + w2 * c0.x;
            v.y = w0 * a0.y + w1 * b0.y + w2 * c0.y;
            v.z = w0 * a1.x + w1 * b1.x + w2 * c1.x;
            v.w = w0 * a1.y + w1 * b1.y + w2 * c1.y;
            *(float4*)&S[nl * SPITCH + 4 * lane] = v;
        }
        __syncthreads();

        #pragma unroll
        for (int mi = 0; mi < 2; ++mi) {
            const int ol = wm * 32 + mi * 16 + (lane >> 2);
            #pragma unroll
            for (int nt = 0; nt < 8; ++nt) {
                const int cl = wn * 64 + nt * 8 + (lane & 3) * 2;
                S[cl * SPITCH + ol]           += acc[mi][nt][0];
                S[(cl + 1) * SPITCH + ol]     += acc[mi][nt][1];
                S[cl * SPITCH + ol + 8]       += acc[mi][nt][2];
                S[(cl + 1) * SPITCH + ol + 8] += acc[mi][nt][3];
            }
        }
        __syncthreads();

        const float4 gm = *(const float4*)&gamma[o0 + 4 * lane];
        const float4 bt = *(const float4*)&beta[o0 + 4 * lane];
        for (int j = 0; j < 16; ++j) {
            const int nl = warp * 16 + j;
            float4 v = *(float4*)&S[nl * SPITCH + 4 * lane];
            v.x = fmaxf(fmaf(v.x, gm.x * inv, bt.x), 0.0f);
            v.y = fmaxf(fmaf(v.y, gm.y * inv, bt.y), 0.0f);
            v.z = fmaxf(fmaf(v.z, gm.z * inv, bt.z), 0.0f);
            v.w = fmaxf(fmaf(v.w, gm.w * inv, bt.w), 0.0f);
            const size_t hb = ((size_t)bz * NPTS + n0 + nl) * CH + o0 + 4 * lane;
            *(__half2*)&g_Hf[hb]     = __floats2half2_rn(v.x, v.y);
            *(__half2*)&g_Hf[hb + 2] = __floats2half2_rn(v.z, v.w);
        }
        return;
    }

    if (MODE == 0) {
        // stage acc -> S, then coalesced fp16 row stores to g_Gh[m][o]
        __syncthreads();
        float* S = (float*)sm;
        #pragma unroll
        for (int mi = 0; mi < 2; ++mi) {
            const int ol = wm * 32 + mi * 16 + (lane >> 2);     // o local
            #pragma unroll
            for (int nt = 0; nt < 8; ++nt) {
                const int cl = wn * 64 + nt * 8 + (lane & 3) * 2; // m local
                S[cl * SPITCH + ol]           = acc[mi][nt][0];
                S[(cl + 1) * SPITCH + ol]     = acc[mi][nt][1];
                S[cl * SPITCH + ol + 8]       = acc[mi][nt][2];
                S[(cl + 1) * SPITCH + ol + 8] = acc[mi][nt][3];
            }
        }
        __syncthreads();

        __half* Gh = g_Gh + (size_t)bz * MPTS * CH;
        const int m0 = blockIdx.x * 128;
        const int o0 = blockIdx.y * 128;
        for (int j = 0; j < 16; ++j) {
            const int r = warp * 16 + j;                        // m local
            float4 v = *(float4*)&S[r * SPITCH + 4 * lane];
            __half2 h0 = __floats2half2_rn(v.x, v.y);
            __half2 h1 = __floats2half2_rn(v.z, v.w);
            *(__half2*)&Gh[(size_t)(m0 + r) * CH + o0 + 4 * lane]     = h0;
            *(__half2*)&Gh[(size_t)(m0 + r) * CH + o0 + 4 * lane + 2] = h1;
        }
        return;
    }

    // MODE 1: BN+ReLU fp32 fragment stores (nt outer -> gamma/beta loaded once)
    float* outB = Out + bz * oBS;
    #pragma unroll
    for (int nt = 0; nt < 8; ++nt) {
        const int c0 = blockIdx.x * 128 + wn * 64 + nt * 8 + (lane & 3) * 2;
        const float s0 = __ldg(&gamma[c0])     * inv;
        const float s1 = __ldg(&gamma[c0 + 1]) * inv;
        const float b0 = __ldg(&beta[c0]);
        const float b1 = __ldg(&beta[c0 + 1]);
        #pragma unroll
        for (int mi = 0; mi < 2; ++mi) {
            const int r0 = blockIdx.y * 128 + wm * 32 + mi * 16 + (lane >> 2);
            float v0 = fmaxf(fmaf(acc[mi][nt][0], s0, b0), 0.0f);
            float v1 = fmaxf(fmaf(acc[mi][nt][1], s1, b1), 0.0f);
            float v2 = fmaxf(fmaf(acc[mi][nt][2], s0, b0), 0.0f);
            float v3 = fmaxf(fmaf(acc[mi][nt][3], s1, b1), 0.0f);
            outB[(size_t)c0       * outLd + r0]     = v0;
            outB[(size_t)(c0 + 1) * outLd + r0]     = v1;
            outB[(size_t)c0       * outLd + r0 + 8] = v2;
            outB[(size_t)(c0 + 1) * outLd + r0 + 8] = v3;
        }
    }
}

// ---------------------------------------------------------------------------
extern "C" void kernel_launch(void* const* d_in, const int* in_sizes, int n_in,
                              void* d_out, int out_size)
{
    const float* xyz1   = (const float*)d_in[0];
    const float* xyz2   = (const float*)d_in[1];
    const float* feat1  = (const float*)d_in[2];
    const float* feat2  = (const float*)d_in[3];
    const float* w1     = (const float*)d_in[4];
    const float* gamma1 = (const float*)d_in[5];
    const float* beta1  = (const float*)d_in[6];
    const float* w2     = (const float*)d_in[7];
    const float* gamma2 = (const float*)d_in[8];
    const float* beta2  = (const float*)d_in[9];
    float* out = (float*)d_out;

    __half *X1f, *X2f, *Hf, *W1af, *W1bf, *W2f;
    cudaGetSymbolAddress((void**)&X1f,  g_X1f);
    cudaGetSymbolAddress((void**)&X2f,  g_X2f);
    cudaGetSymbolAddress((void**)&Hf,   g_Hf);
    cudaGetSymbolAddress((void**)&W1af, g_W1af);
    cudaGetSymbolAddress((void**)&W1bf, g_W1bf);
    cudaGetSymbolAddress((void**)&W2f,  g_W2f);

    cudaFuncSetAttribute(mma_gemm<0>, cudaFuncAttributeMaxDynamicSharedMemorySize, SMEM_GEMM);
    cudaFuncSetAttribute(mma_gemm<1>, cudaFuncAttributeMaxDynamicSharedMemorySize, SMEM_GEMM);
    cudaFuncSetAttribute(mma_gemm<2>, cudaFuncAttributeMaxDynamicSharedMemorySize, SMEM_GEMM);

    // 1. merged prep: kNN + weight converts + feature transposes
    prep_kernel<<<PREP_TOTAL, 256>>>(xyz1, xyz2, feat1, feat2, w1, w2);

    // 2. G[b][m][o] = W1a @ feat2  -> fp16 g_Gh (staged coalesced store)
    mma_gemm<0><<<dim3(MPTS / 128, CH / 128, BB), 256, SMEM_GEMM>>>(
        W1af, 0, 0, X2f, (size_t)MPTS * CH, 1,
        nullptr, 0, 0, nullptr, nullptr);

    // 3. F GEMM fused with interpolation/BN/ReLU -> g_Hf
    mma_gemm<2><<<dim3(NPTS / 128, CH / 128, BB), 256, SMEM_GEMM>>>(
        W1bf, 0, 0, X1f, (size_t)NPTS * CH, 1,
        nullptr, 0, 0, gamma1, beta1);

    // 4. Out[b][o][n] = relu(bn(W2 @ H))
    mma_gemm<1><<<dim3(CH / 128, NPTS / 128, BB), 256, SMEM_GEMM>>>(
        Hf, (size_t)NPTS * CH, 1, W2f, 0, 0,
        out, (size_t)CH * NPTS, NPTS, gamma2, beta2);

    (void)in_sizes; (void)n_in; (void)out_size;
}